// round 7
// baseline (speedup 1.0000x reference)
#include <cuda_runtime.h>
#include <cuda_fp16.h>
#include <math.h>
#include <stdint.h>

#define S_LEN 2048
#define D_DIM 1024
#define H_NUM 16
#define HD_DIM 64
#define FF_DIM 4096
#define DEPTH 2
#define NSEG 4
#define EPS 1e-6f

// ---------------- scratch (device globals; allocation-free) ----------------
__device__ __half g_h  [S_LEN * D_DIM];          // LN output (half)
__device__ float  g_qkv[S_LEN * 3 * D_DIM];      // qkv projection (fp32)
__device__ __half g_ao [S_LEN * D_DIM];          // attention output (half)
__device__ __half g_ff [S_LEN * FF_DIM];         // fc1+gelu output (half)
// half weights
__device__ __half g_wq[DEPTH * D_DIM * 3 * D_DIM];
__device__ __half g_wp[DEPTH * D_DIM * D_DIM];
__device__ __half g_w1[DEPTH * D_DIM * FF_DIM];
__device__ __half g_w2[DEPTH * FF_DIM * D_DIM];

// ---------------- helpers ----------------
__device__ __forceinline__ uint32_t f2tf32(float f) {
    uint32_t r;
    asm("cvt.rna.tf32.f32 %0, %1;" : "=r"(r) : "f"(f));
    return r;
}

__device__ __forceinline__ void mma_tf32(float* d,
                                         uint32_t a0, uint32_t a1, uint32_t a2, uint32_t a3,
                                         uint32_t b0, uint32_t b1) {
    asm volatile(
        "mma.sync.aligned.m16n8k8.row.col.f32.tf32.tf32.f32 "
        "{%0,%1,%2,%3}, {%4,%5,%6,%7}, {%8,%9}, {%0,%1,%2,%3};\n"
        : "+f"(d[0]), "+f"(d[1]), "+f"(d[2]), "+f"(d[3])
        : "r"(a0), "r"(a1), "r"(a2), "r"(a3), "r"(b0), "r"(b1));
}

__device__ __forceinline__ void mma_f16(float* d, const uint32_t* a, const uint32_t* b) {
    asm volatile(
        "mma.sync.aligned.m16n8k16.row.col.f32.f16.f16.f32 "
        "{%0,%1,%2,%3}, {%4,%5,%6,%7}, {%8,%9}, {%0,%1,%2,%3};\n"
        : "+f"(d[0]), "+f"(d[1]), "+f"(d[2]), "+f"(d[3])
        : "r"(a[0]), "r"(a[1]), "r"(a[2]), "r"(a[3]), "r"(b[0]), "r"(b[1]));
}

__device__ __forceinline__ void ldsm_x4(uint32_t* r, const void* p) {
    uint32_t a = (uint32_t)__cvta_generic_to_shared(p);
    asm volatile("ldmatrix.sync.aligned.m8n8.x4.shared.b16 {%0,%1,%2,%3}, [%4];"
                 : "=r"(r[0]), "=r"(r[1]), "=r"(r[2]), "=r"(r[3]) : "r"(a));
}
__device__ __forceinline__ void ldsm_x4_t(uint32_t* r, const void* p) {
    uint32_t a = (uint32_t)__cvta_generic_to_shared(p);
    asm volatile("ldmatrix.sync.aligned.m8n8.x4.trans.shared.b16 {%0,%1,%2,%3}, [%4];"
                 : "=r"(r[0]), "=r"(r[1]), "=r"(r[2]), "=r"(r[3]) : "r"(a));
}

__device__ __forceinline__ void cp16(void* dst, const void* src) {
    uint32_t d = (uint32_t)__cvta_generic_to_shared(dst);
    asm volatile("cp.async.cg.shared.global [%0], [%1], 16;\n" :: "r"(d), "l"(src));
}
__device__ __forceinline__ void cp_commit() {
    asm volatile("cp.async.commit_group;\n");
}

// ---------------- fp32 -> fp16 weight conversion (8 elems/thread) ----------
__global__ void f2h_kernel(const float4* __restrict__ in, uint4* __restrict__ out, int n8) {
    int i = blockIdx.x * blockDim.x + threadIdx.x;
    if (i < n8) {
        float4 a = in[2 * i];
        float4 b = in[2 * i + 1];
        __half2 h0 = __floats2half2_rn(a.x, a.y);
        __half2 h1 = __floats2half2_rn(a.z, a.w);
        __half2 h2 = __floats2half2_rn(b.x, b.y);
        __half2 h3 = __floats2half2_rn(b.z, b.w);
        uint4 o;
        o.x = *(uint32_t*)&h0; o.y = *(uint32_t*)&h1;
        o.z = *(uint32_t*)&h2; o.w = *(uint32_t*)&h3;
        out[i] = o;
    }
}

// ---------------- LayerNorm: one block per row, half output ----------------
__global__ void ln_kernel(const float* __restrict__ x,
                          const float* __restrict__ g,
                          const float* __restrict__ b,
                          __half* __restrict__ out) {
    const int row = blockIdx.x;
    const int tid = threadIdx.x;                // 256 threads
    const float* xr = x + (size_t)row * D_DIM;
    __shared__ float red[256];

    float s = 0.f;
    for (int i = tid; i < D_DIM; i += 256) s += xr[i];
    red[tid] = s; __syncthreads();
    for (int o = 128; o > 0; o >>= 1) { if (tid < o) red[tid] += red[tid + o]; __syncthreads(); }
    const float mean = red[0] * (1.f / D_DIM);
    __syncthreads();

    float v = 0.f;
    for (int i = tid; i < D_DIM; i += 256) { float d = xr[i] - mean; v += d * d; }
    red[tid] = v; __syncthreads();
    for (int o = 128; o > 0; o >>= 1) { if (tid < o) red[tid] += red[tid + o]; __syncthreads(); }
    const float rstd = rsqrtf(red[0] * (1.f / D_DIM) + EPS);

    for (int i = tid; i < D_DIM; i += 256)
        out[(size_t)row * D_DIM + i] = __float2half((xr[i] - mean) * rstd * g[i] + b[i]);
}

// ------------- FP16 GEMM: 128x128 tile, BK=32, 2-stage (proj / fc2) --------
// EPI: 1 = bias + exact GELU (half C), 2 = bias+resid (float C)
template<int EPI, typename CT>
__global__ __launch_bounds__(256)
void gemm_f16_kernel(const __half* __restrict__ A,
                     const __half* __restrict__ B,
                     const float* __restrict__ bias,
                     const float* __restrict__ resid,
                     CT* __restrict__ C,
                     int M, int N, int K) {
    __shared__ __half As[2][128][40];
    __shared__ __half Bs[2][32][136];

    const int tid  = threadIdx.x;
    const int lane = tid & 31;
    const int wid  = tid >> 5;
    const int warp_m = wid & 1;
    const int warp_n = wid >> 1;
    const int g = lane >> 2;
    const int t = lane & 3;

    const int bx = blockIdx.x;
    const int by = blockIdx.y;

    const __half* Ag = A + (size_t)by * 128 * K;
    const __half* Bg = B + (size_t)bx * 128;

    float acc[4][4][4];
    #pragma unroll
    for (int mi = 0; mi < 4; mi++)
        #pragma unroll
        for (int ni = 0; ni < 4; ni++)
            #pragma unroll
            for (int e = 0; e < 4; e++) acc[mi][ni][e] = 0.f;

    const int NIT = K >> 5;

    {
        #pragma unroll
        for (int i = 0; i < 2; i++) {
            int id = tid + 256 * i;
            int r = id >> 2, c = (id & 3) * 8;
            cp16(&As[0][r][c], Ag + (size_t)r * K + c);
        }
        #pragma unroll
        for (int i = 0; i < 2; i++) {
            int id = tid + 256 * i;
            int r = id >> 4, c = (id & 15) * 8;
            cp16(&Bs[0][r][c], Bg + (size_t)r * N + c);
        }
        cp_commit();
    }

    const int a_row = lane & 15;
    const int a_chk = (lane >> 4) * 8;

    #pragma unroll 1
    for (int it = 0; it < NIT; it++) {
        const int buf = it & 1;
        if (it + 1 < NIT) {
            const int k0 = (it + 1) << 5;
            #pragma unroll
            for (int i = 0; i < 2; i++) {
                int id = tid + 256 * i;
                int r = id >> 2, c = (id & 3) * 8;
                cp16(&As[buf ^ 1][r][c], Ag + (size_t)r * K + k0 + c);
            }
            #pragma unroll
            for (int i = 0; i < 2; i++) {
                int id = tid + 256 * i;
                int r = id >> 4, c = (id & 15) * 8;
                cp16(&Bs[buf ^ 1][r][c], Bg + (size_t)(k0 + r) * N + c);
            }
            cp_commit();
            asm volatile("cp.async.wait_group 1;\n");
        } else {
            asm volatile("cp.async.wait_group 0;\n");
        }
        __syncthreads();

        #pragma unroll
        for (int ks = 0; ks < 2; ks++) {
            uint32_t af[4][4], bf[4][2];
            #pragma unroll
            for (int mi = 0; mi < 4; mi++) {
                int row = warp_m * 64 + mi * 16 + a_row;
                ldsm_x4(af[mi], &As[buf][row][ks * 16 + a_chk]);
            }
            #pragma unroll
            for (int p = 0; p < 2; p++) {
                uint32_t r[4];
                int krow = ks * 16 + a_row;
                int ncol = warp_n * 32 + p * 16 + a_chk;
                ldsm_x4_t(r, &Bs[buf][krow][ncol]);
                bf[p * 2][0] = r[0]; bf[p * 2][1] = r[1];
                bf[p * 2 + 1][0] = r[2]; bf[p * 2 + 1][1] = r[3];
            }
            #pragma unroll
            for (int mi = 0; mi < 4; mi++)
                #pragma unroll
                for (int ni = 0; ni < 4; ni++)
                    mma_f16(acc[mi][ni], af[mi], bf[ni]);
        }
        __syncthreads();
    }

    #pragma unroll
    for (int mi = 0; mi < 4; mi++) {
        const int row0 = by * 128 + warp_m * 64 + mi * 16 + g;
        #pragma unroll
        for (int ni = 0; ni < 4; ni++) {
            const int col = bx * 128 + warp_n * 32 + (ni >> 1) * 16 + (ni & 1) * 8 + 2 * t;
            #pragma unroll
            for (int half_ = 0; half_ < 2; half_++) {
                const int r = row0 + half_ * 8;
                #pragma unroll
                for (int e = 0; e < 2; e++) {
                    float v = acc[mi][ni][half_ * 2 + e] + bias[col + e];
                    if (EPI == 1) {
                        v = 0.5f * v * (1.f + erff(v * 0.70710678118654752f));
                    } else if (EPI == 2) {
                        v += resid[(size_t)r * N + col + e];
                    }
                    if (sizeof(CT) == 2) {
                        ((__half*)C)[(size_t)r * N + col + e] = __float2half(v);
                    } else {
                        ((float*)C)[(size_t)r * N + col + e] = v;
                    }
                }
            }
        }
    }
}

// ------- FP16 big GEMM: 128x256 tile, BK=32, 3-stage, dynamic smem ---------
// warp tile 64x64 (2 warps M x 4 warps N). EPI: 0 = bias (float C), 1 = GELU (half C)
#define BIG_AS_BYTES (3 * 128 * 40 * 2)              // 30720
#define BIG_SMEM_BYTES (BIG_AS_BYTES + 3 * 32 * 264 * 2)  // 30720 + 50688 = 81408
template<int EPI, typename CT>
__global__ __launch_bounds__(256)
void gemm_big_kernel(const __half* __restrict__ A,
                     const __half* __restrict__ B,
                     const float* __restrict__ bias,
                     CT* __restrict__ C,
                     int M, int N, int K) {
    extern __shared__ __half smem[];
    typedef __half (*AsT)[128][40];
    typedef __half (*BsT)[32][264];
    AsT As = (AsT)smem;
    BsT Bs = (BsT)(smem + BIG_AS_BYTES / 2);

    const int tid  = threadIdx.x;
    const int lane = tid & 31;
    const int wid  = tid >> 5;
    const int warp_m = wid & 1;     // 2 warps over M (64 each)
    const int warp_n = wid >> 1;    // 4 warps over N (64 each)
    const int g = lane >> 2;
    const int t = lane & 3;

    const int bx = blockIdx.x;
    const int by = blockIdx.y;

    const __half* Ag = A + (size_t)by * 128 * K;
    const __half* Bg = B + (size_t)bx * 256;

    float acc[4][8][4];
    #pragma unroll
    for (int mi = 0; mi < 4; mi++)
        #pragma unroll
        for (int ni = 0; ni < 8; ni++)
            #pragma unroll
            for (int e = 0; e < 4; e++) acc[mi][ni][e] = 0.f;

    const int NIT = K >> 5;

    // prefetch stages 0,1
    #pragma unroll
    for (int st = 0; st < 2; st++) {
        const int k0 = st << 5;
        #pragma unroll
        for (int i = 0; i < 2; i++) {
            int id = tid + 256 * i;
            int r = id >> 2, c = (id & 3) * 8;
            cp16(&As[st][r][c], Ag + (size_t)r * K + k0 + c);
        }
        #pragma unroll
        for (int i = 0; i < 4; i++) {
            int id = tid + 256 * i;
            int r = id >> 5, c = (id & 31) * 8;
            cp16(&Bs[st][r][c], Bg + (size_t)(k0 + r) * N + c);
        }
        cp_commit();
    }

    const int a_row = lane & 15;
    const int a_chk = (lane >> 4) * 8;

    int buf = 0;
    #pragma unroll 1
    for (int it = 0; it < NIT; it++) {
        if (it + 2 < NIT) {
            const int k0 = (it + 2) << 5;
            const int st = (buf + 2) % 3;
            #pragma unroll
            for (int i = 0; i < 2; i++) {
                int id = tid + 256 * i;
                int r = id >> 2, c = (id & 3) * 8;
                cp16(&As[st][r][c], Ag + (size_t)r * K + k0 + c);
            }
            #pragma unroll
            for (int i = 0; i < 4; i++) {
                int id = tid + 256 * i;
                int r = id >> 5, c = (id & 31) * 8;
                cp16(&Bs[st][r][c], Bg + (size_t)(k0 + r) * N + c);
            }
            cp_commit();
            asm volatile("cp.async.wait_group 2;\n");
        } else if (it + 1 < NIT) {
            asm volatile("cp.async.wait_group 1;\n");
        } else {
            asm volatile("cp.async.wait_group 0;\n");
        }
        __syncthreads();

        #pragma unroll
        for (int ks = 0; ks < 2; ks++) {
            uint32_t af[4][4], bf[8][2];
            #pragma unroll
            for (int mi = 0; mi < 4; mi++) {
                int row = warp_m * 64 + mi * 16 + a_row;
                ldsm_x4(af[mi], &As[buf][row][ks * 16 + a_chk]);
            }
            #pragma unroll
            for (int p = 0; p < 4; p++) {
                uint32_t r[4];
                int krow = ks * 16 + a_row;
                int ncol = warp_n * 64 + p * 16 + a_chk;
                ldsm_x4_t(r, &Bs[buf][krow][ncol]);
                bf[p * 2][0] = r[0]; bf[p * 2][1] = r[1];
                bf[p * 2 + 1][0] = r[2]; bf[p * 2 + 1][1] = r[3];
            }
            #pragma unroll
            for (int mi = 0; mi < 4; mi++)
                #pragma unroll
                for (int ni = 0; ni < 8; ni++)
                    mma_f16(acc[mi][ni], af[mi], bf[ni]);
        }
        __syncthreads();

        buf++; if (buf == 3) buf = 0;
    }

    #pragma unroll
    for (int mi = 0; mi < 4; mi++) {
        const int row0 = by * 128 + warp_m * 64 + mi * 16 + g;
        #pragma unroll
        for (int ni = 0; ni < 8; ni++) {
            const int col = bx * 256 + warp_n * 64 + (ni >> 1) * 16 + (ni & 1) * 8 + 2 * t;
            #pragma unroll
            for (int half_ = 0; half_ < 2; half_++) {
                const int r = row0 + half_ * 8;
                #pragma unroll
                for (int e = 0; e < 2; e++) {
                    float v = acc[mi][ni][half_ * 2 + e] + bias[col + e];
                    if (EPI == 1) {
                        v = 0.5f * v * (1.f + erff(v * 0.70710678118654752f));
                    }
                    if (sizeof(CT) == 2) {
                        ((__half*)C)[(size_t)r * N + col + e] = __float2half(v);
                    } else {
                        ((float*)C)[(size_t)r * N + col + e] = v;
                    }
                }
            }
        }
    }
}

// ---------------- RoPE on q and k slices of qkv (fp32) ----------------
__global__ void rope_kernel(float* __restrict__ qkv,
                            const float* __restrict__ cosp,
                            const float* __restrict__ sinp) {
    int idx = blockIdx.x * blockDim.x + threadIdx.x;  // S*H*32
    if (idx >= S_LEN * H_NUM * 32) return;
    const int d = idx & 31;
    const int h = (idx >> 5) & (H_NUM - 1);
    const int s = idx >> (5 + 4);

    const float c1 = cosp[s * 64 + d];
    const float c2 = cosp[s * 64 + d + 32];
    const float s1 = sinp[s * 64 + d];
    const float s2 = sinp[s * 64 + d + 32];

    size_t base = (size_t)s * (3 * D_DIM) + h * HD_DIM + d;
    float q1 = qkv[base], q2 = qkv[base + 32];
    qkv[base]      = q1 * c1 - q2 * s1;
    qkv[base + 32] = q2 * c2 + q1 * s2;
    float k1 = qkv[base + D_DIM], k2 = qkv[base + D_DIM + 32];
    qkv[base + D_DIM]      = k1 * c1 - k2 * s1;
    qkv[base + D_DIM + 32] = k2 * c2 + k1 * s2;
}

// ---------- tensor-core flash attention (tf32), half output ---------
__global__ __launch_bounds__(256)
void attn_kernel(const float* __restrict__ qkv,
                 const int* __restrict__ cu,
                 __half* __restrict__ ao) {
    const int h  = blockIdx.y;
    const int s0 = blockIdx.x * 128;
    const int tid  = threadIdx.x;
    const int lane = tid & 31;
    const int wid  = tid >> 5;
    const int g = lane >> 2;
    const int t = lane & 3;

    __shared__ float Ks[32][68];
    __shared__ float Vs[32][72];
    __shared__ float Ps[128][36];

    int start = 0, len = S_LEN;
    #pragma unroll
    for (int i = 0; i < NSEG; i++) {
        int a = cu[i], b = cu[i + 1];
        if (s0 >= a && s0 < b) { start = a; len = b - a; }
    }

    uint32_t qf[8][4];
    {
        const float* q0 = qkv + (size_t)(s0 + wid * 16 + g) * (3 * D_DIM) + h * HD_DIM;
        const float* q8 = q0 + 8 * (3 * D_DIM);
        #pragma unroll
        for (int ks = 0; ks < 8; ks++) {
            qf[ks][0] = f2tf32(q0[8 * ks + t]     * 0.125f);
            qf[ks][1] = f2tf32(q8[8 * ks + t]     * 0.125f);
            qf[ks][2] = f2tf32(q0[8 * ks + t + 4] * 0.125f);
            qf[ks][3] = f2tf32(q8[8 * ks + t + 4] * 0.125f);
        }
    }

    float m0 = -3.4e38f, m1 = -3.4e38f, l0 = 0.f, l1 = 0.f;
    float out[8][4];
    #pragma unroll
    for (int n = 0; n < 8; n++)
        #pragma unroll
        for (int e = 0; e < 4; e++) out[n][e] = 0.f;

    const int pr = wid * 16;
    const int nch = len >> 5;
    for (int c = 0; c < nch; c++) {
        const int kb = start + c * 32;
        #pragma unroll
        for (int i = 0; i < 2; i++) {
            int id = tid + 256 * i;
            int r = id >> 4, c4 = (id & 15) * 4;
            const float* base = qkv + (size_t)(kb + r) * (3 * D_DIM) + h * HD_DIM + c4;
            float4 kv = *(const float4*)(base + D_DIM);
            float4 vv = *(const float4*)(base + 2 * D_DIM);
            Ks[r][c4 + 0] = __uint_as_float(f2tf32(kv.x));
            Ks[r][c4 + 1] = __uint_as_float(f2tf32(kv.y));
            Ks[r][c4 + 2] = __uint_as_float(f2tf32(kv.z));
            Ks[r][c4 + 3] = __uint_as_float(f2tf32(kv.w));
            Vs[r][c4 + 0] = __uint_as_float(f2tf32(vv.x));
            Vs[r][c4 + 1] = __uint_as_float(f2tf32(vv.y));
            Vs[r][c4 + 2] = __uint_as_float(f2tf32(vv.z));
            Vs[r][c4 + 3] = __uint_as_float(f2tf32(vv.w));
        }
        __syncthreads();

        float sacc[4][4];
        #pragma unroll
        for (int j = 0; j < 4; j++)
            #pragma unroll
            for (int e = 0; e < 4; e++) sacc[j][e] = 0.f;
        #pragma unroll
        for (int ks = 0; ks < 8; ks++) {
            #pragma unroll
            for (int j = 0; j < 4; j++) {
                uint32_t b0 = __float_as_uint(Ks[8 * j + g][8 * ks + t]);
                uint32_t b1 = __float_as_uint(Ks[8 * j + g][8 * ks + t + 4]);
                mma_tf32(sacc[j], qf[ks][0], qf[ks][1], qf[ks][2], qf[ks][3], b0, b1);
            }
        }

        float ml0 = -3.4e38f, ml1 = -3.4e38f;
        #pragma unroll
        for (int j = 0; j < 4; j++) {
            ml0 = fmaxf(ml0, fmaxf(sacc[j][0], sacc[j][1]));
            ml1 = fmaxf(ml1, fmaxf(sacc[j][2], sacc[j][3]));
        }
        ml0 = fmaxf(ml0, __shfl_xor_sync(0xffffffffu, ml0, 1));
        ml0 = fmaxf(ml0, __shfl_xor_sync(0xffffffffu, ml0, 2));
        ml1 = fmaxf(ml1, __shfl_xor_sync(0xffffffffu, ml1, 1));
        ml1 = fmaxf(ml1, __shfl_xor_sync(0xffffffffu, ml1, 2));
        const float mn0 = fmaxf(m0, ml0);
        const float mn1 = fmaxf(m1, ml1);
        const float f0 = __expf(m0 - mn0);
        const float f1 = __expf(m1 - mn1);

        float ll0 = 0.f, ll1 = 0.f;
        #pragma unroll
        for (int j = 0; j < 4; j++) {
            float p0 = __expf(sacc[j][0] - mn0);
            float p1 = __expf(sacc[j][1] - mn0);
            float p2 = __expf(sacc[j][2] - mn1);
            float p3 = __expf(sacc[j][3] - mn1);
            ll0 += p0 + p1; ll1 += p2 + p3;
            Ps[pr + g    ][8 * j + 2 * t]     = __uint_as_float(f2tf32(p0));
            Ps[pr + g    ][8 * j + 2 * t + 1] = __uint_as_float(f2tf32(p1));
            Ps[pr + g + 8][8 * j + 2 * t]     = __uint_as_float(f2tf32(p2));
            Ps[pr + g + 8][8 * j + 2 * t + 1] = __uint_as_float(f2tf32(p3));
        }
        ll0 += __shfl_xor_sync(0xffffffffu, ll0, 1);
        ll0 += __shfl_xor_sync(0xffffffffu, ll0, 2);
        ll1 += __shfl_xor_sync(0xffffffffu, ll1, 1);
        ll1 += __shfl_xor_sync(0xffffffffu, ll1, 2);
        l0 = l0 * f0 + ll0;
        l1 = l1 * f1 + ll1;
        m0 = mn0; m1 = mn1;
        #pragma unroll
        for (int n = 0; n < 8; n++) {
            out[n][0] *= f0; out[n][1] *= f0;
            out[n][2] *= f1; out[n][3] *= f1;
        }
        __syncwarp();

        #pragma unroll
        for (int ks = 0; ks < 4; ks++) {
            uint32_t a0 = __float_as_uint(Ps[pr + g    ][8 * ks + t]);
            uint32_t a1 = __float_as_uint(Ps[pr + g + 8][8 * ks + t]);
            uint32_t a2 = __float_as_uint(Ps[pr + g    ][8 * ks + t + 4]);
            uint32_t a3 = __float_as_uint(Ps[pr + g + 8][8 * ks + t + 4]);
            #pragma unroll
            for (int n = 0; n < 8; n++) {
                uint32_t b0 = __float_as_uint(Vs[8 * ks + t    ][8 * n + g]);
                uint32_t b1 = __float_as_uint(Vs[8 * ks + t + 4][8 * n + g]);
                mma_tf32(out[n], a0, a1, a2, a3, b0, b1);
            }
        }
        __syncthreads();
    }

    const float i0 = 1.f / l0;
    const float i1 = 1.f / l1;
    __half* o0 = ao + (size_t)(s0 + pr + g) * D_DIM + h * HD_DIM;
    __half* o8 = o0 + 8 * D_DIM;
    #pragma unroll
    for (int n = 0; n < 8; n++) {
        *(__half2*)(o0 + 8 * n + 2 * t) = __floats2half2_rn(out[n][0] * i0, out[n][1] * i0);
        *(__half2*)(o8 + 8 * n + 2 * t) = __floats2half2_rn(out[n][2] * i1, out[n][3] * i1);
    }
}

// ---------------- driver ----------------
extern "C" void kernel_launch(void* const* d_in, const int* in_sizes, int n_in,
                              void* d_out, int out_size) {
    const float* hidden = (const float*)d_in[0];
    const int*   cu     = (const int*)d_in[1];
    const float* cosp   = (const float*)d_in[2];
    const float* sinp   = (const float*)d_in[3];
    const float* ln1_g  = (const float*)d_in[4];
    const float* ln1_b  = (const float*)d_in[5];
    const float* qkv_w  = (const float*)d_in[6];
    const float* qkv_b  = (const float*)d_in[7];
    const float* proj_w = (const float*)d_in[8];
    const float* proj_b = (const float*)d_in[9];
    const float* ln2_g  = (const float*)d_in[10];
    const float* ln2_b  = (const float*)d_in[11];
    const float* fc1_w  = (const float*)d_in[12];
    const float* fc1_b  = (const float*)d_in[13];
    const float* fc2_w  = (const float*)d_in[14];
    const float* fc2_b  = (const float*)d_in[15];

    float* x = (float*)d_out;

    __half *h, *ao, *ff, *wq, *wp, *w1, *w2;
    float *qkv;
    cudaGetSymbolAddress((void**)&h,   g_h);
    cudaGetSymbolAddress((void**)&qkv, g_qkv);
    cudaGetSymbolAddress((void**)&ao,  g_ao);
    cudaGetSymbolAddress((void**)&ff,  g_ff);
    cudaGetSymbolAddress((void**)&wq,  g_wq);
    cudaGetSymbolAddress((void**)&wp,  g_wp);
    cudaGetSymbolAddress((void**)&w1,  g_w1);
    cudaGetSymbolAddress((void**)&w2,  g_w2);

    // allow >48KB dynamic smem for the big GEMM (idempotent host call)
    cudaFuncSetAttribute(gemm_big_kernel<0, float>,
                         cudaFuncAttributeMaxDynamicSharedMemorySize, BIG_SMEM_BYTES);
    cudaFuncSetAttribute(gemm_big_kernel<1, __half>,
                         cudaFuncAttributeMaxDynamicSharedMemorySize, BIG_SMEM_BYTES);

    // weight conversions (fp32 -> fp16), once per launch
    {
        int n8;
        n8 = DEPTH * D_DIM * 3 * D_DIM / 8;
        f2h_kernel<<<(n8 + 255) / 256, 256>>>((const float4*)qkv_w, (uint4*)wq, n8);
        n8 = DEPTH * D_DIM * D_DIM / 8;
        f2h_kernel<<<(n8 + 255) / 256, 256>>>((const float4*)proj_w, (uint4*)wp, n8);
        n8 = DEPTH * D_DIM * FF_DIM / 8;
        f2h_kernel<<<(n8 + 255) / 256, 256>>>((const float4*)fc1_w, (uint4*)w1, n8);
        n8 = DEPTH * FF_DIM * D_DIM / 8;
        f2h_kernel<<<(n8 + 255) / 256, 256>>>((const float4*)fc2_w, (uint4*)w2, n8);
    }

    cudaMemcpyAsync(x, hidden, (size_t)S_LEN * D_DIM * sizeof(float),
                    cudaMemcpyDeviceToDevice);

    for (int i = 0; i < DEPTH; i++) {
        const __half* wqi = wq + (size_t)i * D_DIM * 3 * D_DIM;
        const float*  qb  = qkv_b  + (size_t)i * 3 * D_DIM;
        const __half* wpi = wp + (size_t)i * D_DIM * D_DIM;
        const float*  pb  = proj_b + (size_t)i * D_DIM;
        const __half* w1i = w1 + (size_t)i * D_DIM * FF_DIM;
        const float*  f1b = fc1_b  + (size_t)i * FF_DIM;
        const __half* w2i = w2 + (size_t)i * FF_DIM * D_DIM;
        const float*  f2b = fc2_b  + (size_t)i * D_DIM;

        ln_kernel<<<S_LEN, 256>>>(x, ln1_g + (size_t)i * D_DIM, ln1_b + (size_t)i * D_DIM, h);

        {   // qkv = h @ qkv_w + qkv_b  (fp32 out, big tile)
            dim3 grid(3 * D_DIM / 256, S_LEN / 128);
            gemm_big_kernel<0, float><<<grid, 256, BIG_SMEM_BYTES>>>(
                h, wqi, qb, qkv, S_LEN, 3 * D_DIM, D_DIM);
        }

        {   // RoPE
            int total = S_LEN * H_NUM * 32;
            rope_kernel<<<(total + 255) / 256, 256>>>(qkv, cosp, sinp);
        }

        {   // attention -> half ao
            dim3 grid(S_LEN / 128, H_NUM);
            attn_kernel<<<grid, 256>>>(qkv, cu, ao);
        }

        {   // x += ao @ proj_w + proj_b  (fp32 out)
            dim3 grid(D_DIM / 128, S_LEN / 128);
            gemm_f16_kernel<2, float><<<grid, 256>>>(ao, wpi, pb, x, x,
                                                     S_LEN, D_DIM, D_DIM);
        }

        ln_kernel<<<S_LEN, 256>>>(x, ln2_g + (size_t)i * D_DIM, ln2_b + (size_t)i * D_DIM, h);

        {   // ff = gelu(h @ fc1_w + fc1_b)  (half out, big tile)
            dim3 grid(FF_DIM / 256, S_LEN / 128);
            gemm_big_kernel<1, __half><<<grid, 256, BIG_SMEM_BYTES>>>(
                h, w1i, f1b, ff, S_LEN, FF_DIM, D_DIM);
        }

        {   // x += ff @ fc2_w + fc2_b  (fp32 out)
            dim3 grid(D_DIM / 128, S_LEN / 128);
            gemm_f16_kernel<2, float><<<grid, 256>>>(ff, w2i, f2b, x, x,
                                                     S_LEN, D_DIM, FF_DIM);
        }
    }
}

// round 9
// speedup vs baseline: 1.1472x; 1.1472x over previous
#include <cuda_runtime.h>
#include <cuda_fp16.h>
#include <math.h>
#include <stdint.h>

#define S_LEN 2048
#define D_DIM 1024
#define H_NUM 16
#define HD_DIM 64
#define FF_DIM 4096
#define DEPTH 2
#define NSEG 4
#define EPS 1e-6f

// ---------------- scratch (device globals; allocation-free) ----------------
__device__ __half g_h  [S_LEN * D_DIM];          // LN output (half)
__device__ float  g_qkv[S_LEN * 3 * D_DIM];      // qkv projection (fp32)
__device__ __half g_ao [S_LEN * D_DIM];          // attention output (half)
__device__ __half g_ff [S_LEN * FF_DIM];         // fc1+gelu output (half)
// half weights [K, N] row-major
__device__ __half g_wq[DEPTH * D_DIM * 3 * D_DIM];
__device__ __half g_wp[DEPTH * D_DIM * D_DIM];
__device__ __half g_w1[DEPTH * D_DIM * FF_DIM];
__device__ __half g_w2[DEPTH * FF_DIM * D_DIM];

// ---------------- helpers ----------------
__device__ __forceinline__ void mma_f16(float* d, const uint32_t* a, const uint32_t* b) {
    asm volatile(
        "mma.sync.aligned.m16n8k16.row.col.f32.f16.f16.f32 "
        "{%0,%1,%2,%3}, {%4,%5,%6,%7}, {%8,%9}, {%0,%1,%2,%3};\n"
        : "+f"(d[0]), "+f"(d[1]), "+f"(d[2]), "+f"(d[3])
        : "r"(a[0]), "r"(a[1]), "r"(a[2]), "r"(a[3]), "r"(b[0]), "r"(b[1]));
}
__device__ __forceinline__ void mma_f16_2(float* d,
                                          uint32_t a0, uint32_t a1, uint32_t a2, uint32_t a3,
                                          uint32_t b0, uint32_t b1) {
    asm volatile(
        "mma.sync.aligned.m16n8k16.row.col.f32.f16.f16.f32 "
        "{%0,%1,%2,%3}, {%4,%5,%6,%7}, {%8,%9}, {%0,%1,%2,%3};\n"
        : "+f"(d[0]), "+f"(d[1]), "+f"(d[2]), "+f"(d[3])
        : "r"(a0), "r"(a1), "r"(a2), "r"(a3), "r"(b0), "r"(b1));
}
__device__ __forceinline__ void ldsm_x4(uint32_t* r, const void* p) {
    uint32_t a = (uint32_t)__cvta_generic_to_shared(p);
    asm volatile("ldmatrix.sync.aligned.m8n8.x4.shared.b16 {%0,%1,%2,%3}, [%4];"
                 : "=r"(r[0]), "=r"(r[1]), "=r"(r[2]), "=r"(r[3]) : "r"(a));
}
__device__ __forceinline__ void ldsm_x4_t(uint32_t* r, const void* p) {
    uint32_t a = (uint32_t)__cvta_generic_to_shared(p);
    asm volatile("ldmatrix.sync.aligned.m8n8.x4.trans.shared.b16 {%0,%1,%2,%3}, [%4];"
                 : "=r"(r[0]), "=r"(r[1]), "=r"(r[2]), "=r"(r[3]) : "r"(a));
}
__device__ __forceinline__ void cp16(void* dst, const void* src) {
    uint32_t d = (uint32_t)__cvta_generic_to_shared(dst);
    asm volatile("cp.async.cg.shared.global [%0], [%1], 16;\n" :: "r"(d), "l"(src));
}
__device__ __forceinline__ void cp_commit() {
    asm volatile("cp.async.commit_group;\n");
}
__device__ __forceinline__ uint32_t h2pack(float a, float b) {
    __half2 h = __floats2half2_rn(a, b);
    return *(uint32_t*)&h;
}

// ---------------- fp32 -> fp16 weight conversion (8 elems/thread) ----------
__global__ void f2h_kernel(const float4* __restrict__ in, uint4* __restrict__ out, int n8) {
    int i = blockIdx.x * blockDim.x + threadIdx.x;
    if (i < n8) {
        float4 a = in[2 * i];
        float4 b = in[2 * i + 1];
        __half2 h0 = __floats2half2_rn(a.x, a.y);
        __half2 h1 = __floats2half2_rn(a.z, a.w);
        __half2 h2 = __floats2half2_rn(b.x, b.y);
        __half2 h3 = __floats2half2_rn(b.z, b.w);
        uint4 o;
        o.x = *(uint32_t*)&h0; o.y = *(uint32_t*)&h1;
        o.z = *(uint32_t*)&h2; o.w = *(uint32_t*)&h3;
        out[i] = o;
    }
}

// ---------------- LayerNorm: one block per row, half output ----------------
__global__ void ln_kernel(const float* __restrict__ x,
                          const float* __restrict__ g,
                          const float* __restrict__ b,
                          __half* __restrict__ out) {
    const int row = blockIdx.x;
    const int tid = threadIdx.x;                // 256 threads
    const float* xr = x + (size_t)row * D_DIM;
    __shared__ float red[256];

    float s = 0.f;
    for (int i = tid; i < D_DIM; i += 256) s += xr[i];
    red[tid] = s; __syncthreads();
    for (int o = 128; o > 0; o >>= 1) { if (tid < o) red[tid] += red[tid + o]; __syncthreads(); }
    const float mean = red[0] * (1.f / D_DIM);
    __syncthreads();

    float v = 0.f;
    for (int i = tid; i < D_DIM; i += 256) { float d = xr[i] - mean; v += d * d; }
    red[tid] = v; __syncthreads();
    for (int o = 128; o > 0; o >>= 1) { if (tid < o) red[tid] += red[tid + o]; __syncthreads(); }
    const float rstd = rsqrtf(red[0] * (1.f / D_DIM) + EPS);

    for (int i = tid; i < D_DIM; i += 256)
        out[(size_t)row * D_DIM + i] = __float2half((xr[i] - mean) * rstd * g[i] + b[i]);
}

// ------------- FP16 GEMM: 128x128 tile, BK=32, 3-stage cp.async ------------
// EPI: 0 = bias (float C), 1 = bias + exact GELU (half C), 2 = bias+resid (float C)
#define G3_AS_HALFS (3 * 128 * 40)
#define G3_SMEM_BYTES ((3 * 128 * 40 + 3 * 32 * 136) * 2)   // 56832
template<int EPI, typename CT>
__global__ __launch_bounds__(256)
void gemm_f16_kernel(const __half* __restrict__ A,
                     const __half* __restrict__ B,
                     const float* __restrict__ bias,
                     const float* __restrict__ resid,
                     CT* __restrict__ C,
                     int M, int N, int K) {
    extern __shared__ __half gsm[];
    __half (*As)[128][40] = (__half(*)[128][40])gsm;
    __half (*Bs)[32][136] = (__half(*)[32][136])(gsm + G3_AS_HALFS);

    const int tid  = threadIdx.x;
    const int lane = tid & 31;
    const int wid  = tid >> 5;
    const int warp_m = wid & 1;
    const int warp_n = wid >> 1;
    const int g = lane >> 2;
    const int t = lane & 3;

    const int bx = blockIdx.x;
    const int by = blockIdx.y;

    const __half* Ag = A + (size_t)by * 128 * K;
    const __half* Bg = B + (size_t)bx * 128;

    float acc[4][4][4];
    #pragma unroll
    for (int mi = 0; mi < 4; mi++)
        #pragma unroll
        for (int ni = 0; ni < 4; ni++)
            #pragma unroll
            for (int e = 0; e < 4; e++) acc[mi][ni][e] = 0.f;

    const int NIT = K >> 5;

    auto load_stage = [&](int st, int k0) {
        #pragma unroll
        for (int i = 0; i < 2; i++) {
            int id = tid + 256 * i;
            int r = id >> 2, c = (id & 3) * 8;
            cp16(&As[st][r][c], Ag + (size_t)r * K + k0 + c);
        }
        #pragma unroll
        for (int i = 0; i < 2; i++) {
            int id = tid + 256 * i;
            int r = id >> 4, c = (id & 15) * 8;
            cp16(&Bs[st][r][c], Bg + (size_t)(k0 + r) * N + c);
        }
        cp_commit();
    };

    load_stage(0, 0);
    load_stage(1, 32);

    const int a_row = lane & 15;
    const int a_chk = (lane >> 4) * 8;

    int buf = 0;
    #pragma unroll 1
    for (int it = 0; it < NIT; it++) {
        if (it + 2 < NIT) {
            load_stage((buf + 2) % 3, (it + 2) << 5);
            asm volatile("cp.async.wait_group 2;\n");
        } else if (it + 1 < NIT) {
            asm volatile("cp.async.wait_group 1;\n");
        } else {
            asm volatile("cp.async.wait_group 0;\n");
        }
        __syncthreads();

        #pragma unroll
        for (int ks = 0; ks < 2; ks++) {
            uint32_t af[4][4], bf[4][2];
            #pragma unroll
            for (int mi = 0; mi < 4; mi++) {
                int row = warp_m * 64 + mi * 16 + a_row;
                ldsm_x4(af[mi], &As[buf][row][ks * 16 + a_chk]);
            }
            #pragma unroll
            for (int p = 0; p < 2; p++) {
                uint32_t r[4];
                int krow = ks * 16 + a_row;
                int ncol = warp_n * 32 + p * 16 + a_chk;
                ldsm_x4_t(r, &Bs[buf][krow][ncol]);
                bf[p * 2][0] = r[0]; bf[p * 2][1] = r[1];
                bf[p * 2 + 1][0] = r[2]; bf[p * 2 + 1][1] = r[3];
            }
            #pragma unroll
            for (int mi = 0; mi < 4; mi++)
                #pragma unroll
                for (int ni = 0; ni < 4; ni++)
                    mma_f16(acc[mi][ni], af[mi], bf[ni]);
        }
        __syncthreads();
        buf++; if (buf == 3) buf = 0;
    }

    #pragma unroll
    for (int mi = 0; mi < 4; mi++) {
        const int row0 = by * 128 + warp_m * 64 + mi * 16 + g;
        #pragma unroll
        for (int ni = 0; ni < 4; ni++) {
            const int col = bx * 128 + warp_n * 32 + (ni >> 1) * 16 + (ni & 1) * 8 + 2 * t;
            #pragma unroll
            for (int half_ = 0; half_ < 2; half_++) {
                const int r = row0 + half_ * 8;
                #pragma unroll
                for (int e = 0; e < 2; e++) {
                    float v = acc[mi][ni][half_ * 2 + e] + bias[col + e];
                    if (EPI == 1) {
                        v = 0.5f * v * (1.f + erff(v * 0.70710678118654752f));
                    } else if (EPI == 2) {
                        v += resid[(size_t)r * N + col + e];
                    }
                    if (sizeof(CT) == 2) {
                        ((__half*)C)[(size_t)r * N + col + e] = __float2half(v);
                    } else {
                        ((float*)C)[(size_t)r * N + col + e] = v;
                    }
                }
            }
        }
    }
}

// ---------------- RoPE on q and k slices of qkv (fp32) ----------------
__global__ void rope_kernel(float* __restrict__ qkv,
                            const float* __restrict__ cosp,
                            const float* __restrict__ sinp) {
    int idx = blockIdx.x * blockDim.x + threadIdx.x;  // S*H*32
    if (idx >= S_LEN * H_NUM * 32) return;
    const int d = idx & 31;
    const int h = (idx >> 5) & (H_NUM - 1);
    const int s = idx >> (5 + 4);

    const float c1 = cosp[s * 64 + d];
    const float c2 = cosp[s * 64 + d + 32];
    const float s1 = sinp[s * 64 + d];
    const float s2 = sinp[s * 64 + d + 32];

    size_t base = (size_t)s * (3 * D_DIM) + h * HD_DIM + d;
    float q1 = qkv[base], q2 = qkv[base + 32];
    qkv[base]      = q1 * c1 - q2 * s1;
    qkv[base + 32] = q2 * c2 + q1 * s2;
    float k1 = qkv[base + D_DIM], k2 = qkv[base + D_DIM + 32];
    qkv[base + D_DIM]      = k1 * c1 - k2 * s1;
    qkv[base + D_DIM + 32] = k2 * c2 + k1 * s2;
}

// ---------- fp16 tensor-core flash attention: block = (128 q-rows, head) ----
// 8 warps; warp w owns rows 16w..16w+15. P stays in registers (acc layout ==
// A-frag layout). fp32 accumulate everywhere.
__global__ __launch_bounds__(256)
void attn_kernel(const float* __restrict__ qkv,
                 const int* __restrict__ cu,
                 __half* __restrict__ ao) {
    const int h  = blockIdx.y;
    const int s0 = blockIdx.x * 128;
    const int tid  = threadIdx.x;
    const int lane = tid & 31;
    const int wid  = tid >> 5;
    const int g = lane >> 2;
    const int t = lane & 3;
    const int a_row = lane & 15;
    const int a_chk = (lane >> 4) * 8;

    __shared__ __half Kh[32][72];
    __shared__ __half Vh[32][72];

    int start = 0, len = S_LEN;
    #pragma unroll
    for (int i = 0; i < NSEG; i++) {
        int a = cu[i], b = cu[i + 1];
        if (s0 >= a && s0 < b) { start = a; len = b - a; }
    }

    const int pr = wid * 16;

    // Q A-frags (half, pre-scaled): qf[dchunk][0..3]
    uint32_t qf[4][4];
    {
        const float* q0 = qkv + (size_t)(s0 + pr + g) * (3 * D_DIM) + h * HD_DIM;
        const float* q8 = q0 + 8 * (3 * D_DIM);
        #pragma unroll
        for (int dc = 0; dc < 4; dc++) {
            const int c = dc * 16 + 2 * t;
            float2 v0 = *(const float2*)(q0 + c);
            float2 v1 = *(const float2*)(q8 + c);
            float2 v2 = *(const float2*)(q0 + c + 8);
            float2 v3 = *(const float2*)(q8 + c + 8);
            qf[dc][0] = h2pack(v0.x * 0.125f, v0.y * 0.125f);
            qf[dc][1] = h2pack(v1.x * 0.125f, v1.y * 0.125f);
            qf[dc][2] = h2pack(v2.x * 0.125f, v2.y * 0.125f);
            qf[dc][3] = h2pack(v3.x * 0.125f, v3.y * 0.125f);
        }
    }

    float m0 = -3.4e38f, m1 = -3.4e38f, l0 = 0.f, l1 = 0.f;
    float out[8][4];
    #pragma unroll
    for (int n = 0; n < 8; n++)
        #pragma unroll
        for (int e = 0; e < 4; e++) out[n][e] = 0.f;

    const int nch = len >> 5;
    for (int c = 0; c < nch; c++) {
        const int kb = start + c * 32;
        // load K,V chunk (fp32 -> half) : thread r=tid>>3 (key), c8=(tid&7)*8
        {
            const int r = tid >> 3;
            const int c8 = (tid & 7) * 8;
            const float* base = qkv + (size_t)(kb + r) * (3 * D_DIM) + h * HD_DIM + c8;
            float4 k0 = *(const float4*)(base + D_DIM);
            float4 k1 = *(const float4*)(base + D_DIM + 4);
            float4 v0 = *(const float4*)(base + 2 * D_DIM);
            float4 v1 = *(const float4*)(base + 2 * D_DIM + 4);
            uint4 kk, vv;
            kk.x = h2pack(k0.x, k0.y); kk.y = h2pack(k0.z, k0.w);
            kk.z = h2pack(k1.x, k1.y); kk.w = h2pack(k1.z, k1.w);
            vv.x = h2pack(v0.x, v0.y); vv.y = h2pack(v0.z, v0.w);
            vv.z = h2pack(v1.x, v1.y); vv.w = h2pack(v1.z, v1.w);
            *(uint4*)&Kh[r][c8] = kk;
            *(uint4*)&Vh[r][c8] = vv;
        }
        __syncthreads();

        // S = Q @ K^T  : sacc[j] covers keys 8j..8j+7
        float sacc[4][4];
        #pragma unroll
        for (int j = 0; j < 4; j++)
            #pragma unroll
            for (int e = 0; e < 4; e++) sacc[j][e] = 0.f;
        #pragma unroll
        for (int dc = 0; dc < 4; dc++) {
            #pragma unroll
            for (int kh = 0; kh < 2; kh++) {
                uint32_t r[4];
                ldsm_x4(r, &Kh[kh * 16 + a_row][dc * 16 + a_chk]);
                mma_f16_2(sacc[kh * 2],     qf[dc][0], qf[dc][1], qf[dc][2], qf[dc][3],
                          r[0], r[2]);
                mma_f16_2(sacc[kh * 2 + 1], qf[dc][0], qf[dc][1], qf[dc][2], qf[dc][3],
                          r[1], r[3]);
            }
        }

        // online softmax
        float ml0 = -3.4e38f, ml1 = -3.4e38f;
        #pragma unroll
        for (int j = 0; j < 4; j++) {
            ml0 = fmaxf(ml0, fmaxf(sacc[j][0], sacc[j][1]));
            ml1 = fmaxf(ml1, fmaxf(sacc[j][2], sacc[j][3]));
        }
        ml0 = fmaxf(ml0, __shfl_xor_sync(0xffffffffu, ml0, 1));
        ml0 = fmaxf(ml0, __shfl_xor_sync(0xffffffffu, ml0, 2));
        ml1 = fmaxf(ml1, __shfl_xor_sync(0xffffffffu, ml1, 1));
        ml1 = fmaxf(ml1, __shfl_xor_sync(0xffffffffu, ml1, 2));
        const float mn0 = fmaxf(m0, ml0);
        const float mn1 = fmaxf(m1, ml1);
        const float f0 = __expf(m0 - mn0);
        const float f1 = __expf(m1 - mn1);

        // P packed straight into A-frags: pa[kchunk][0..3]
        uint32_t pa[2][4];
        float ll0 = 0.f, ll1 = 0.f;
        #pragma unroll
        for (int j = 0; j < 4; j++) {
            float p0 = __expf(sacc[j][0] - mn0);
            float p1 = __expf(sacc[j][1] - mn0);
            float p2 = __expf(sacc[j][2] - mn1);
            float p3 = __expf(sacc[j][3] - mn1);
            ll0 += p0 + p1; ll1 += p2 + p3;
            pa[j >> 1][(j & 1) * 2]     = h2pack(p0, p1);
            pa[j >> 1][(j & 1) * 2 + 1] = h2pack(p2, p3);
        }
        ll0 += __shfl_xor_sync(0xffffffffu, ll0, 1);
        ll0 += __shfl_xor_sync(0xffffffffu, ll0, 2);
        ll1 += __shfl_xor_sync(0xffffffffu, ll1, 1);
        ll1 += __shfl_xor_sync(0xffffffffu, ll1, 2);
        l0 = l0 * f0 + ll0;
        l1 = l1 * f1 + ll1;
        m0 = mn0; m1 = mn1;
        #pragma unroll
        for (int n = 0; n < 8; n++) {
            out[n][0] *= f0; out[n][1] *= f0;
            out[n][2] *= f1; out[n][3] *= f1;
        }

        // out += P @ V   (V as B: ldsm trans on [key][dim])
        #pragma unroll
        for (int kc = 0; kc < 2; kc++) {
            #pragma unroll
            for (int p = 0; p < 4; p++) {
                uint32_t r[4];
                ldsm_x4_t(r, &Vh[kc * 16 + a_row][p * 16 + a_chk]);
                mma_f16(out[p * 2],     pa[kc], r);          // b = {r0, r1}
                mma_f16_2(out[p * 2 + 1], pa[kc][0], pa[kc][1], pa[kc][2], pa[kc][3],
                          r[2], r[3]);
            }
        }
        __syncthreads();
    }

    const float i0 = 1.f / l0;
    const float i1 = 1.f / l1;
    __half* o0 = ao + (size_t)(s0 + pr + g) * D_DIM + h * HD_DIM;
    __half* o8 = o0 + 8 * D_DIM;
    #pragma unroll
    for (int n = 0; n < 8; n++) {
        *(__half2*)(o0 + 8 * n + 2 * t) = __floats2half2_rn(out[n][0] * i0, out[n][1] * i0);
        *(__half2*)(o8 + 8 * n + 2 * t) = __floats2half2_rn(out[n][2] * i1, out[n][3] * i1);
    }
}

// ---------------- driver ----------------
extern "C" void kernel_launch(void* const* d_in, const int* in_sizes, int n_in,
                              void* d_out, int out_size) {
    const float* hidden = (const float*)d_in[0];
    const int*   cu     = (const int*)d_in[1];
    const float* cosp   = (const float*)d_in[2];
    const float* sinp   = (const float*)d_in[3];
    const float* ln1_g  = (const float*)d_in[4];
    const float* ln1_b  = (const float*)d_in[5];
    const float* qkv_w  = (const float*)d_in[6];
    const float* qkv_b  = (const float*)d_in[7];
    const float* proj_w = (const float*)d_in[8];
    const float* proj_b = (const float*)d_in[9];
    const float* ln2_g  = (const float*)d_in[10];
    const float* ln2_b  = (const float*)d_in[11];
    const float* fc1_w  = (const float*)d_in[12];
    const float* fc1_b  = (const float*)d_in[13];
    const float* fc2_w  = (const float*)d_in[14];
    const float* fc2_b  = (const float*)d_in[15];

    float* x = (float*)d_out;

    __half *h, *ao, *ff, *wq, *wp, *w1, *w2;
    float *qkv;
    cudaGetSymbolAddress((void**)&h,   g_h);
    cudaGetSymbolAddress((void**)&qkv, g_qkv);
    cudaGetSymbolAddress((void**)&ao,  g_ao);
    cudaGetSymbolAddress((void**)&ff,  g_ff);
    cudaGetSymbolAddress((void**)&wq,  g_wq);
    cudaGetSymbolAddress((void**)&wp,  g_wp);
    cudaGetSymbolAddress((void**)&w1,  g_w1);
    cudaGetSymbolAddress((void**)&w2,  g_w2);

    cudaFuncSetAttribute(gemm_f16_kernel<0, float>,
                         cudaFuncAttributeMaxDynamicSharedMemorySize, G3_SMEM_BYTES);
    cudaFuncSetAttribute(gemm_f16_kernel<1, __half>,
                         cudaFuncAttributeMaxDynamicSharedMemorySize, G3_SMEM_BYTES);
    cudaFuncSetAttribute(gemm_f16_kernel<2, float>,
                         cudaFuncAttributeMaxDynamicSharedMemorySize, G3_SMEM_BYTES);

    // weight conversions (fp32 -> fp16), once per launch
    {
        int n8;
        n8 = DEPTH * D_DIM * 3 * D_DIM / 8;
        f2h_kernel<<<(n8 + 255) / 256, 256>>>((const float4*)qkv_w, (uint4*)wq, n8);
        n8 = DEPTH * D_DIM * D_DIM / 8;
        f2h_kernel<<<(n8 + 255) / 256, 256>>>((const float4*)proj_w, (uint4*)wp, n8);
        n8 = DEPTH * D_DIM * FF_DIM / 8;
        f2h_kernel<<<(n8 + 255) / 256, 256>>>((const float4*)fc1_w, (uint4*)w1, n8);
        n8 = DEPTH * FF_DIM * D_DIM / 8;
        f2h_kernel<<<(n8 + 255) / 256, 256>>>((const float4*)fc2_w, (uint4*)w2, n8);
    }

    cudaMemcpyAsync(x, hidden, (size_t)S_LEN * D_DIM * sizeof(float),
                    cudaMemcpyDeviceToDevice);

    for (int i = 0; i < DEPTH; i++) {
        const __half* wqi = wq + (size_t)i * D_DIM * 3 * D_DIM;
        const float*  qb  = qkv_b  + (size_t)i * 3 * D_DIM;
        const __half* wpi = wp + (size_t)i * D_DIM * D_DIM;
        const float*  pb  = proj_b + (size_t)i * D_DIM;
        const __half* w1i = w1 + (size_t)i * D_DIM * FF_DIM;
        const float*  f1b = fc1_b  + (size_t)i * FF_DIM;
        const __half* w2i = w2 + (size_t)i * FF_DIM * D_DIM;
        const float*  f2b = fc2_b  + (size_t)i * D_DIM;

        ln_kernel<<<S_LEN, 256>>>(x, ln1_g + (size_t)i * D_DIM, ln1_b + (size_t)i * D_DIM, h);

        {   // qkv = h @ qkv_w + qkv_b  (fp32 out)
            dim3 grid(3 * D_DIM / 128, S_LEN / 128);
            gemm_f16_kernel<0, float><<<grid, 256, G3_SMEM_BYTES>>>(
                h, wqi, qb, nullptr, qkv, S_LEN, 3 * D_DIM, D_DIM);
        }

        {   // RoPE
            int total = S_LEN * H_NUM * 32;
            rope_kernel<<<(total + 255) / 256, 256>>>(qkv, cosp, sinp);
        }

        {   // attention -> half ao
            dim3 grid(S_LEN / 128, H_NUM);
            attn_kernel<<<grid, 256>>>(qkv, cu, ao);
        }

        {   // x += ao @ proj_w + proj_b  (fp32 out)
            dim3 grid(D_DIM / 128, S_LEN / 128);
            gemm_f16_kernel<2, float><<<grid, 256, G3_SMEM_BYTES>>>(
                ao, wpi, pb, x, x, S_LEN, D_DIM, D_DIM);
        }

        ln_kernel<<<S_LEN, 256>>>(x, ln2_g + (size_t)i * D_DIM, ln2_b + (size_t)i * D_DIM, h);

        {   // ff = gelu(h @ fc1_w + fc1_b)  (half out)
            dim3 grid(FF_DIM / 128, S_LEN / 128);
            gemm_f16_kernel<1, __half><<<grid, 256, G3_SMEM_BYTES>>>(
                h, w1i, f1b, nullptr, ff, S_LEN, FF_DIM, D_DIM);
        }

        {   // x += ff @ fc2_w + fc2_b  (fp32 out)
            dim3 grid(D_DIM / 128, S_LEN / 128);
            gemm_f16_kernel<2, float><<<grid, 256, G3_SMEM_BYTES>>>(
                ff, w2i, f2b, x, x, S_LEN, D_DIM, FF_DIM);
        }
    }
}

// round 10
// speedup vs baseline: 1.2989x; 1.1323x over previous
#include <cuda_runtime.h>
#include <cuda_fp16.h>
#include <math.h>
#include <stdint.h>

#define S_LEN 2048
#define D_DIM 1024
#define H_NUM 16
#define HD_DIM 64
#define FF_DIM 4096
#define DEPTH 2
#define NSEG 4
#define EPS 1e-6f

// ---------------- scratch (device globals; allocation-free) ----------------
__device__ __half g_h  [S_LEN * D_DIM];          // LN output (half)
__device__ __half g_qkv[S_LEN * 3 * D_DIM];      // qkv projection (half)
__device__ __half g_ao [S_LEN * D_DIM];          // attention output (half)
__device__ __half g_ff [S_LEN * FF_DIM];         // fc1+gelu output (half)
// half weights [K, N] row-major
__device__ __half g_wq[DEPTH * D_DIM * 3 * D_DIM];
__device__ __half g_wp[DEPTH * D_DIM * D_DIM];
__device__ __half g_w1[DEPTH * D_DIM * FF_DIM];
__device__ __half g_w2[DEPTH * FF_DIM * D_DIM];

// ---------------- helpers ----------------
__device__ __forceinline__ void mma_f16(float* d, const uint32_t* a, const uint32_t* b) {
    asm volatile(
        "mma.sync.aligned.m16n8k16.row.col.f32.f16.f16.f32 "
        "{%0,%1,%2,%3}, {%4,%5,%6,%7}, {%8,%9}, {%0,%1,%2,%3};\n"
        : "+f"(d[0]), "+f"(d[1]), "+f"(d[2]), "+f"(d[3])
        : "r"(a[0]), "r"(a[1]), "r"(a[2]), "r"(a[3]), "r"(b[0]), "r"(b[1]));
}
__device__ __forceinline__ void mma_f16_2(float* d,
                                          uint32_t a0, uint32_t a1, uint32_t a2, uint32_t a3,
                                          uint32_t b0, uint32_t b1) {
    asm volatile(
        "mma.sync.aligned.m16n8k16.row.col.f32.f16.f16.f32 "
        "{%0,%1,%2,%3}, {%4,%5,%6,%7}, {%8,%9}, {%0,%1,%2,%3};\n"
        : "+f"(d[0]), "+f"(d[1]), "+f"(d[2]), "+f"(d[3])
        : "r"(a0), "r"(a1), "r"(a2), "r"(a3), "r"(b0), "r"(b1));
}
__device__ __forceinline__ void ldsm_x4(uint32_t* r, const void* p) {
    uint32_t a = (uint32_t)__cvta_generic_to_shared(p);
    asm volatile("ldmatrix.sync.aligned.m8n8.x4.shared.b16 {%0,%1,%2,%3}, [%4];"
                 : "=r"(r[0]), "=r"(r[1]), "=r"(r[2]), "=r"(r[3]) : "r"(a));
}
__device__ __forceinline__ void ldsm_x4_t(uint32_t* r, const void* p) {
    uint32_t a = (uint32_t)__cvta_generic_to_shared(p);
    asm volatile("ldmatrix.sync.aligned.m8n8.x4.trans.shared.b16 {%0,%1,%2,%3}, [%4];"
                 : "=r"(r[0]), "=r"(r[1]), "=r"(r[2]), "=r"(r[3]) : "r"(a));
}
__device__ __forceinline__ void cp16(void* dst, const void* src) {
    uint32_t d = (uint32_t)__cvta_generic_to_shared(dst);
    asm volatile("cp.async.cg.shared.global [%0], [%1], 16;\n" :: "r"(d), "l"(src));
}
__device__ __forceinline__ void cp_commit() {
    asm volatile("cp.async.commit_group;\n");
}
__device__ __forceinline__ uint32_t h2pack(float a, float b) {
    __half2 h = __floats2half2_rn(a, b);
    return *(uint32_t*)&h;
}

// ------------- fused fp32 -> fp16 conversion, 16 elems/thread --------------
__device__ __forceinline__ void cvt16(const float4* s, uint4* d, int j) {
    float4 a = s[4 * j], b = s[4 * j + 1], c = s[4 * j + 2], e = s[4 * j + 3];
    uint4 o0, o1;
    o0.x = h2pack(a.x, a.y); o0.y = h2pack(a.z, a.w);
    o0.z = h2pack(b.x, b.y); o0.w = h2pack(b.z, b.w);
    o1.x = h2pack(c.x, c.y); o1.y = h2pack(c.z, c.w);
    o1.z = h2pack(e.x, e.y); o1.w = h2pack(e.z, e.w);
    d[2 * j] = o0; d[2 * j + 1] = o1;
}
__global__ void f2h_all_kernel(const float* w0, __half* o0, int n0,   // in 16-elem units
                               const float* w1, __half* o1, int n1,
                               const float* w2, __half* o2, int n2,
                               const float* w3, __half* o3, int n3) {
    int i = blockIdx.x * blockDim.x + threadIdx.x;
    if (i < n0) { cvt16((const float4*)w0, (uint4*)o0, i); return; }
    i -= n0;
    if (i < n1) { cvt16((const float4*)w1, (uint4*)o1, i); return; }
    i -= n1;
    if (i < n2) { cvt16((const float4*)w2, (uint4*)o2, i); return; }
    i -= n2;
    if (i < n3) { cvt16((const float4*)w3, (uint4*)o3, i); }
}

// ---------------- LayerNorm: one WARP per row, half output -----------------
__global__ __launch_bounds__(256)
void ln_kernel(const float* __restrict__ x,
               const float* __restrict__ g,
               const float* __restrict__ b,
               __half* __restrict__ out) {
    const int lane = threadIdx.x & 31;
    const int row  = blockIdx.x * 8 + (threadIdx.x >> 5);
    const float* xr = x + (size_t)row * D_DIM;

    float4 v[8];
    float s = 0.f;
    #pragma unroll
    for (int i = 0; i < 8; i++) {
        v[i] = *(const float4*)(xr + i * 128 + lane * 4);
        s += v[i].x + v[i].y + v[i].z + v[i].w;
    }
    #pragma unroll
    for (int o = 16; o > 0; o >>= 1) s += __shfl_xor_sync(0xffffffffu, s, o);
    const float mean = s * (1.f / D_DIM);

    float var = 0.f;
    #pragma unroll
    for (int i = 0; i < 8; i++) {
        float dx = v[i].x - mean, dy = v[i].y - mean;
        float dz = v[i].z - mean, dw = v[i].w - mean;
        var += dx * dx + dy * dy + dz * dz + dw * dw;
    }
    #pragma unroll
    for (int o = 16; o > 0; o >>= 1) var += __shfl_xor_sync(0xffffffffu, var, o);
    const float rstd = rsqrtf(var * (1.f / D_DIM) + EPS);

    __half* orow = out + (size_t)row * D_DIM;
    #pragma unroll
    for (int i = 0; i < 8; i++) {
        const int col = i * 128 + lane * 4;
        float4 gv = *(const float4*)(g + col);
        float4 bv = *(const float4*)(b + col);
        uint2 o;
        o.x = h2pack((v[i].x - mean) * rstd * gv.x + bv.x,
                     (v[i].y - mean) * rstd * gv.y + bv.y);
        o.y = h2pack((v[i].z - mean) * rstd * gv.z + bv.z,
                     (v[i].w - mean) * rstd * gv.w + bv.w);
        *(uint2*)(orow + col) = o;
    }
}

// ------------- FP16 GEMM: 128x128 tile, BK=32, 3-stage cp.async ------------
// EPI: 0 = bias (CT out), 1 = bias + exact GELU (half C), 2 = bias+resid (float C)
#define G3_AS_HALFS (3 * 128 * 40)
#define G3_SMEM_BYTES ((3 * 128 * 40 + 3 * 32 * 136) * 2)   // 56832
template<int EPI, typename CT>
__global__ __launch_bounds__(256)
void gemm_f16_kernel(const __half* __restrict__ A,
                     const __half* __restrict__ B,
                     const float* __restrict__ bias,
                     const float* __restrict__ resid,
                     CT* __restrict__ C,
                     int M, int N, int K) {
    extern __shared__ __half gsm[];
    __half (*As)[128][40] = (__half(*)[128][40])gsm;
    __half (*Bs)[32][136] = (__half(*)[32][136])(gsm + G3_AS_HALFS);

    const int tid  = threadIdx.x;
    const int lane = tid & 31;
    const int wid  = tid >> 5;
    const int warp_m = wid & 1;
    const int warp_n = wid >> 1;
    const int g = lane >> 2;
    const int t = lane & 3;

    const int bx = blockIdx.x;
    const int by = blockIdx.y;

    const __half* Ag = A + (size_t)by * 128 * K;
    const __half* Bg = B + (size_t)bx * 128;

    float acc[4][4][4];
    #pragma unroll
    for (int mi = 0; mi < 4; mi++)
        #pragma unroll
        for (int ni = 0; ni < 4; ni++)
            #pragma unroll
            for (int e = 0; e < 4; e++) acc[mi][ni][e] = 0.f;

    const int NIT = K >> 5;

    auto load_stage = [&](int st, int k0) {
        #pragma unroll
        for (int i = 0; i < 2; i++) {
            int id = tid + 256 * i;
            int r = id >> 2, c = (id & 3) * 8;
            cp16(&As[st][r][c], Ag + (size_t)r * K + k0 + c);
        }
        #pragma unroll
        for (int i = 0; i < 2; i++) {
            int id = tid + 256 * i;
            int r = id >> 4, c = (id & 15) * 8;
            cp16(&Bs[st][r][c], Bg + (size_t)(k0 + r) * N + c);
        }
        cp_commit();
    };

    load_stage(0, 0);
    load_stage(1, 32);

    const int a_row = lane & 15;
    const int a_chk = (lane >> 4) * 8;

    int buf = 0;
    #pragma unroll 1
    for (int it = 0; it < NIT; it++) {
        if (it + 2 < NIT) {
            load_stage((buf + 2) % 3, (it + 2) << 5);
            asm volatile("cp.async.wait_group 2;\n");
        } else if (it + 1 < NIT) {
            asm volatile("cp.async.wait_group 1;\n");
        } else {
            asm volatile("cp.async.wait_group 0;\n");
        }
        __syncthreads();

        #pragma unroll
        for (int ks = 0; ks < 2; ks++) {
            uint32_t af[4][4], bf[4][2];
            #pragma unroll
            for (int mi = 0; mi < 4; mi++) {
                int row = warp_m * 64 + mi * 16 + a_row;
                ldsm_x4(af[mi], &As[buf][row][ks * 16 + a_chk]);
            }
            #pragma unroll
            for (int p = 0; p < 2; p++) {
                uint32_t r[4];
                int krow = ks * 16 + a_row;
                int ncol = warp_n * 32 + p * 16 + a_chk;
                ldsm_x4_t(r, &Bs[buf][krow][ncol]);
                bf[p * 2][0] = r[0]; bf[p * 2][1] = r[1];
                bf[p * 2 + 1][0] = r[2]; bf[p * 2 + 1][1] = r[3];
            }
            #pragma unroll
            for (int mi = 0; mi < 4; mi++)
                #pragma unroll
                for (int ni = 0; ni < 4; ni++)
                    mma_f16(acc[mi][ni], af[mi], bf[ni]);
        }
        __syncthreads();
        buf++; if (buf == 3) buf = 0;
    }

    #pragma unroll
    for (int mi = 0; mi < 4; mi++) {
        const int row0 = by * 128 + warp_m * 64 + mi * 16 + g;
        #pragma unroll
        for (int ni = 0; ni < 4; ni++) {
            const int col = bx * 128 + warp_n * 32 + (ni >> 1) * 16 + (ni & 1) * 8 + 2 * t;
            #pragma unroll
            for (int half_ = 0; half_ < 2; half_++) {
                const int r = row0 + half_ * 8;
                float v0 = acc[mi][ni][half_ * 2]     + bias[col];
                float v1 = acc[mi][ni][half_ * 2 + 1] + bias[col + 1];
                if (EPI == 1) {
                    v0 = 0.5f * v0 * (1.f + erff(v0 * 0.70710678118654752f));
                    v1 = 0.5f * v1 * (1.f + erff(v1 * 0.70710678118654752f));
                } else if (EPI == 2) {
                    const float* rr = resid + (size_t)r * N + col;
                    v0 += rr[0]; v1 += rr[1];
                }
                if (sizeof(CT) == 2) {
                    *(uint32_t*)((__half*)C + (size_t)r * N + col) = h2pack(v0, v1);
                } else {
                    ((float*)C)[(size_t)r * N + col]     = v0;
                    ((float*)C)[(size_t)r * N + col + 1] = v1;
                }
            }
        }
    }
}

// ---------------- RoPE on q and k slices of half qkv ----------------
// thread handles 2 adjacent dims (d2, d2+1) for both q and k of one (s, head)
__global__ void rope_kernel(__half* __restrict__ qkv,
                            const float* __restrict__ cosp,
                            const float* __restrict__ sinp) {
    int idx = blockIdx.x * blockDim.x + threadIdx.x;  // S*H*16
    if (idx >= S_LEN * H_NUM * 16) return;
    const int d2 = (idx & 15) * 2;
    const int h = (idx >> 4) & (H_NUM - 1);
    const int s = idx >> 8;

    const float2 c1 = *(const float2*)(cosp + s * 64 + d2);
    const float2 c2 = *(const float2*)(cosp + s * 64 + d2 + 32);
    const float2 s1 = *(const float2*)(sinp + s * 64 + d2);
    const float2 s2 = *(const float2*)(sinp + s * 64 + d2 + 32);

    __half* base = qkv + (size_t)s * (3 * D_DIM) + h * HD_DIM + d2;
    #pragma unroll
    for (int qk = 0; qk < 2; qk++) {
        __half* p = base + qk * D_DIM;
        float2 a = __half22float2(*(__half2*)p);
        float2 bv = __half22float2(*(__half2*)(p + 32));
        *(uint32_t*)p        = h2pack(a.x * c1.x - bv.x * s1.x,
                                      a.y * c1.y - bv.y * s1.y);
        *(uint32_t*)(p + 32) = h2pack(bv.x * c2.x + a.x * s2.x,
                                      bv.y * c2.y + a.y * s2.y);
    }
}

// ---- fp16 flash attention, double-buffered cp.async K/V chunks ----
__global__ __launch_bounds__(256)
void attn_kernel(const __half* __restrict__ qkv,
                 const int* __restrict__ cu,
                 __half* __restrict__ ao) {
    const int h  = blockIdx.y;
    const int s0 = blockIdx.x * 128;
    const int tid  = threadIdx.x;
    const int lane = tid & 31;
    const int wid  = tid >> 5;
    const int g = lane >> 2;
    const int t = lane & 3;
    const int a_row = lane & 15;
    const int a_chk = (lane >> 4) * 8;

    __shared__ __half Kh[2][32][72];
    __shared__ __half Vh[2][32][72];

    int start = 0, len = S_LEN;
    #pragma unroll
    for (int i = 0; i < NSEG; i++) {
        int a = cu[i], b = cu[i + 1];
        if (s0 >= a && s0 < b) { start = a; len = b - a; }
    }

    const int pr = wid * 16;

    // Q A-frags straight from half qkv (scale applied to S later)
    uint32_t qf[4][4];
    {
        const __half* q0 = qkv + (size_t)(s0 + pr + g) * (3 * D_DIM) + h * HD_DIM;
        const __half* q8 = q0 + 8 * (3 * D_DIM);
        #pragma unroll
        for (int dc = 0; dc < 4; dc++) {
            const int c = dc * 16 + 2 * t;
            qf[dc][0] = *(const uint32_t*)(q0 + c);
            qf[dc][1] = *(const uint32_t*)(q8 + c);
            qf[dc][2] = *(const uint32_t*)(q0 + c + 8);
            qf[dc][3] = *(const uint32_t*)(q8 + c + 8);
        }
    }

    float m0 = -3.4e38f, m1 = -3.4e38f, l0 = 0.f, l1 = 0.f;
    float out[8][4];
    #pragma unroll
    for (int n = 0; n < 8; n++)
        #pragma unroll
        for (int e = 0; e < 4; e++) out[n][e] = 0.f;

    const int kr = tid >> 3;
    const int kc8 = (tid & 7) * 8;
    auto load_chunk = [&](int buf, int kb) {
        const __half* base = qkv + (size_t)(kb + kr) * (3 * D_DIM) + h * HD_DIM + kc8;
        cp16(&Kh[buf][kr][kc8], base + D_DIM);
        cp16(&Vh[buf][kr][kc8], base + 2 * D_DIM);
        cp_commit();
    };

    load_chunk(0, start);

    const int nch = len >> 5;
    for (int c = 0; c < nch; c++) {
        const int buf = c & 1;
        asm volatile("cp.async.wait_group 0;\n");
        __syncthreads();
        if (c + 1 < nch) load_chunk(buf ^ 1, start + (c + 1) * 32);

        // S = Q @ K^T
        float sacc[4][4];
        #pragma unroll
        for (int j = 0; j < 4; j++)
            #pragma unroll
            for (int e = 0; e < 4; e++) sacc[j][e] = 0.f;
        #pragma unroll
        for (int dc = 0; dc < 4; dc++) {
            #pragma unroll
            for (int kh = 0; kh < 2; kh++) {
                uint32_t r[4];
                ldsm_x4(r, &Kh[buf][kh * 16 + a_row][dc * 16 + a_chk]);
                mma_f16_2(sacc[kh * 2],     qf[dc][0], qf[dc][1], qf[dc][2], qf[dc][3],
                          r[0], r[2]);
                mma_f16_2(sacc[kh * 2 + 1], qf[dc][0], qf[dc][1], qf[dc][2], qf[dc][3],
                          r[1], r[3]);
            }
        }
        #pragma unroll
        for (int j = 0; j < 4; j++)
            #pragma unroll
            for (int e = 0; e < 4; e++) sacc[j][e] *= 0.125f;

        // online softmax
        float ml0 = -3.4e38f, ml1 = -3.4e38f;
        #pragma unroll
        for (int j = 0; j < 4; j++) {
            ml0 = fmaxf(ml0, fmaxf(sacc[j][0], sacc[j][1]));
            ml1 = fmaxf(ml1, fmaxf(sacc[j][2], sacc[j][3]));
        }
        ml0 = fmaxf(ml0, __shfl_xor_sync(0xffffffffu, ml0, 1));
        ml0 = fmaxf(ml0, __shfl_xor_sync(0xffffffffu, ml0, 2));
        ml1 = fmaxf(ml1, __shfl_xor_sync(0xffffffffu, ml1, 1));
        ml1 = fmaxf(ml1, __shfl_xor_sync(0xffffffffu, ml1, 2));
        const float mn0 = fmaxf(m0, ml0);
        const float mn1 = fmaxf(m1, ml1);
        const float f0 = __expf(m0 - mn0);
        const float f1 = __expf(m1 - mn1);

        uint32_t pa[2][4];
        float ll0 = 0.f, ll1 = 0.f;
        #pragma unroll
        for (int j = 0; j < 4; j++) {
            float p0 = __expf(sacc[j][0] - mn0);
            float p1 = __expf(sacc[j][1] - mn0);
            float p2 = __expf(sacc[j][2] - mn1);
            float p3 = __expf(sacc[j][3] - mn1);
            ll0 += p0 + p1; ll1 += p2 + p3;
            pa[j >> 1][(j & 1) * 2]     = h2pack(p0, p1);
            pa[j >> 1][(j & 1) * 2 + 1] = h2pack(p2, p3);
        }
        ll0 += __shfl_xor_sync(0xffffffffu, ll0, 1);
        ll0 += __shfl_xor_sync(0xffffffffu, ll0, 2);
        ll1 += __shfl_xor_sync(0xffffffffu, ll1, 1);
        ll1 += __shfl_xor_sync(0xffffffffu, ll1, 2);
        l0 = l0 * f0 + ll0;
        l1 = l1 * f1 + ll1;
        m0 = mn0; m1 = mn1;
        #pragma unroll
        for (int n = 0; n < 8; n++) {
            out[n][0] *= f0; out[n][1] *= f0;
            out[n][2] *= f1; out[n][3] *= f1;
        }

        // out += P @ V
        #pragma unroll
        for (int kc = 0; kc < 2; kc++) {
            #pragma unroll
            for (int p = 0; p < 4; p++) {
                uint32_t r[4];
                ldsm_x4_t(r, &Vh[buf][kc * 16 + a_row][p * 16 + a_chk]);
                mma_f16(out[p * 2], pa[kc], r);
                mma_f16_2(out[p * 2 + 1], pa[kc][0], pa[kc][1], pa[kc][2], pa[kc][3],
                          r[2], r[3]);
            }
        }
    }

    const float i0 = 1.f / l0;
    const float i1 = 1.f / l1;
    __half* o0 = ao + (size_t)(s0 + pr + g) * D_DIM + h * HD_DIM;
    __half* o8 = o0 + 8 * D_DIM;
    #pragma unroll
    for (int n = 0; n < 8; n++) {
        *(uint32_t*)(o0 + 8 * n + 2 * t) = h2pack(out[n][0] * i0, out[n][1] * i0);
        *(uint32_t*)(o8 + 8 * n + 2 * t) = h2pack(out[n][2] * i1, out[n][3] * i1);
    }
}

// ---------------- driver ----------------
extern "C" void kernel_launch(void* const* d_in, const int* in_sizes, int n_in,
                              void* d_out, int out_size) {
    const float* hidden = (const float*)d_in[0];
    const int*   cu     = (const int*)d_in[1];
    const float* cosp   = (const float*)d_in[2];
    const float* sinp   = (const float*)d_in[3];
    const float* ln1_g  = (const float*)d_in[4];
    const float* ln1_b  = (const float*)d_in[5];
    const float* qkv_w  = (const float*)d_in[6];
    const float* qkv_b  = (const float*)d_in[7];
    const float* proj_w = (const float*)d_in[8];
    const float* proj_b = (const float*)d_in[9];
    const float* ln2_g  = (const float*)d_in[10];
    const float* ln2_b  = (const float*)d_in[11];
    const float* fc1_w  = (const float*)d_in[12];
    const float* fc1_b  = (const float*)d_in[13];
    const float* fc2_w  = (const float*)d_in[14];
    const float* fc2_b  = (const float*)d_in[15];

    float* x = (float*)d_out;

    __half *h, *qkv, *ao, *ff, *wq, *wp, *w1, *w2;
    cudaGetSymbolAddress((void**)&h,   g_h);
    cudaGetSymbolAddress((void**)&qkv, g_qkv);
    cudaGetSymbolAddress((void**)&ao,  g_ao);
    cudaGetSymbolAddress((void**)&ff,  g_ff);
    cudaGetSymbolAddress((void**)&wq,  g_wq);
    cudaGetSymbolAddress((void**)&wp,  g_wp);
    cudaGetSymbolAddress((void**)&w1,  g_w1);
    cudaGetSymbolAddress((void**)&w2,  g_w2);

    cudaFuncSetAttribute(gemm_f16_kernel<0, __half>,
                         cudaFuncAttributeMaxDynamicSharedMemorySize, G3_SMEM_BYTES);
    cudaFuncSetAttribute(gemm_f16_kernel<1, __half>,
                         cudaFuncAttributeMaxDynamicSharedMemorySize, G3_SMEM_BYTES);
    cudaFuncSetAttribute(gemm_f16_kernel<2, float>,
                         cudaFuncAttributeMaxDynamicSharedMemorySize, G3_SMEM_BYTES);

    // fused weight conversion (fp32 -> fp16), 16 elems/thread
    {
        const int n0 = DEPTH * D_DIM * 3 * D_DIM / 16;
        const int n1 = DEPTH * D_DIM * D_DIM / 16;
        const int n2 = DEPTH * D_DIM * FF_DIM / 16;
        const int n3 = DEPTH * FF_DIM * D_DIM / 16;
        const int total = n0 + n1 + n2 + n3;
        f2h_all_kernel<<<(total + 255) / 256, 256>>>(
            qkv_w, wq, n0, proj_w, wp, n1, fc1_w, w1, n2, fc2_w, w2, n3);
    }

    cudaMemcpyAsync(x, hidden, (size_t)S_LEN * D_DIM * sizeof(float),
                    cudaMemcpyDeviceToDevice);

    for (int i = 0; i < DEPTH; i++) {
        const __half* wqi = wq + (size_t)i * D_DIM * 3 * D_DIM;
        const float*  qb  = qkv_b  + (size_t)i * 3 * D_DIM;
        const __half* wpi = wp + (size_t)i * D_DIM * D_DIM;
        const float*  pb  = proj_b + (size_t)i * D_DIM;
        const __half* w1i = w1 + (size_t)i * D_DIM * FF_DIM;
        const float*  f1b = fc1_b  + (size_t)i * FF_DIM;
        const __half* w2i = w2 + (size_t)i * FF_DIM * D_DIM;
        const float*  f2b = fc2_b  + (size_t)i * D_DIM;

        ln_kernel<<<S_LEN / 8, 256>>>(x, ln1_g + (size_t)i * D_DIM,
                                      ln1_b + (size_t)i * D_DIM, h);

        {   // qkv = h @ qkv_w + qkv_b  (half out)
            dim3 grid(3 * D_DIM / 128, S_LEN / 128);
            gemm_f16_kernel<0, __half><<<grid, 256, G3_SMEM_BYTES>>>(
                h, wqi, qb, nullptr, qkv, S_LEN, 3 * D_DIM, D_DIM);
        }

        {   // RoPE (half)
            int total = S_LEN * H_NUM * 16;
            rope_kernel<<<(total + 255) / 256, 256>>>(qkv, cosp, sinp);
        }

        {   // attention -> half ao
            dim3 grid(S_LEN / 128, H_NUM);
            attn_kernel<<<grid, 256>>>(qkv, cu, ao);
        }

        {   // x += ao @ proj_w + proj_b  (fp32 out)
            dim3 grid(D_DIM / 128, S_LEN / 128);
            gemm_f16_kernel<2, float><<<grid, 256, G3_SMEM_BYTES>>>(
                ao, wpi, pb, x, x, S_LEN, D_DIM, D_DIM);
        }

        ln_kernel<<<S_LEN / 8, 256>>>(x, ln2_g + (size_t)i * D_DIM,
                                      ln2_b + (size_t)i * D_DIM, h);

        {   // ff = gelu(h @ fc1_w + fc1_b)  (half out)
            dim3 grid(FF_DIM / 128, S_LEN / 128);
            gemm_f16_kernel<1, __half><<<grid, 256, G3_SMEM_BYTES>>>(
                h, w1i, f1b, nullptr, ff, S_LEN, FF_DIM, D_DIM);
        }

        {   // x += ff @ fc2_w + fc2_b  (fp32 out)
            dim3 grid(D_DIM / 128, S_LEN / 128);
            gemm_f16_kernel<2, float><<<grid, 256, G3_SMEM_BYTES>>>(
                ff, w2i, f2b, x, x, S_LEN, D_DIM, FF_DIM);
        }
    }
}

// round 11
// speedup vs baseline: 1.4220x; 1.0948x over previous
#include <cuda_runtime.h>
#include <cuda_fp16.h>
#include <math.h>
#include <stdint.h>

#define S_LEN 2048
#define D_DIM 1024
#define H_NUM 16
#define HD_DIM 64
#define FF_DIM 4096
#define DEPTH 2
#define NSEG 4
#define EPS 1e-6f

// ---------------- scratch (device globals; allocation-free) ----------------
__device__ __half g_h  [S_LEN * D_DIM];          // LN output (half)
__device__ __half g_qkv[S_LEN * 3 * D_DIM];      // qkv projection (half)
__device__ __half g_ao [S_LEN * D_DIM];          // attention output (half)
__device__ __half g_ff [S_LEN * FF_DIM];         // fc1+gelu output (half)
// half weights [K, N] row-major
__device__ __half g_wq[DEPTH * D_DIM * 3 * D_DIM];
__device__ __half g_wp[DEPTH * D_DIM * D_DIM];
__device__ __half g_w1[DEPTH * D_DIM * FF_DIM];
__device__ __half g_w2[DEPTH * FF_DIM * D_DIM];

// ---------------- helpers ----------------
__device__ __forceinline__ void mma_f16(float* d, const uint32_t* a, const uint32_t* b) {
    asm volatile(
        "mma.sync.aligned.m16n8k16.row.col.f32.f16.f16.f32 "
        "{%0,%1,%2,%3}, {%4,%5,%6,%7}, {%8,%9}, {%0,%1,%2,%3};\n"
        : "+f"(d[0]), "+f"(d[1]), "+f"(d[2]), "+f"(d[3])
        : "r"(a[0]), "r"(a[1]), "r"(a[2]), "r"(a[3]), "r"(b[0]), "r"(b[1]));
}
__device__ __forceinline__ void mma_f16_2(float* d,
                                          uint32_t a0, uint32_t a1, uint32_t a2, uint32_t a3,
                                          uint32_t b0, uint32_t b1) {
    asm volatile(
        "mma.sync.aligned.m16n8k16.row.col.f32.f16.f16.f32 "
        "{%0,%1,%2,%3}, {%4,%5,%6,%7}, {%8,%9}, {%0,%1,%2,%3};\n"
        : "+f"(d[0]), "+f"(d[1]), "+f"(d[2]), "+f"(d[3])
        : "r"(a0), "r"(a1), "r"(a2), "r"(a3), "r"(b0), "r"(b1));
}
__device__ __forceinline__ void ldsm_x4(uint32_t* r, const void* p) {
    uint32_t a = (uint32_t)__cvta_generic_to_shared(p);
    asm volatile("ldmatrix.sync.aligned.m8n8.x4.shared.b16 {%0,%1,%2,%3}, [%4];"
                 : "=r"(r[0]), "=r"(r[1]), "=r"(r[2]), "=r"(r[3]) : "r"(a));
}
__device__ __forceinline__ void ldsm_x4_t(uint32_t* r, const void* p) {
    uint32_t a = (uint32_t)__cvta_generic_to_shared(p);
    asm volatile("ldmatrix.sync.aligned.m8n8.x4.trans.shared.b16 {%0,%1,%2,%3}, [%4];"
                 : "=r"(r[0]), "=r"(r[1]), "=r"(r[2]), "=r"(r[3]) : "r"(a));
}
__device__ __forceinline__ void cp16(void* dst, const void* src) {
    uint32_t d = (uint32_t)__cvta_generic_to_shared(dst);
    asm volatile("cp.async.cg.shared.global [%0], [%1], 16;\n" :: "r"(d), "l"(src));
}
__device__ __forceinline__ void cp_commit() {
    asm volatile("cp.async.commit_group;\n");
}
__device__ __forceinline__ uint32_t h2pack(float a, float b) {
    __half2 h = __floats2half2_rn(a, b);
    return *(uint32_t*)&h;
}

// ------------- fused fp32 -> fp16 conversion, 16 elems/thread --------------
__device__ __forceinline__ void cvt16(const float4* s, uint4* d, int j) {
    float4 a = s[4 * j], b = s[4 * j + 1], c = s[4 * j + 2], e = s[4 * j + 3];
    uint4 o0, o1;
    o0.x = h2pack(a.x, a.y); o0.y = h2pack(a.z, a.w);
    o0.z = h2pack(b.x, b.y); o0.w = h2pack(b.z, b.w);
    o1.x = h2pack(c.x, c.y); o1.y = h2pack(c.z, c.w);
    o1.z = h2pack(e.x, e.y); o1.w = h2pack(e.z, e.w);
    d[2 * j] = o0; d[2 * j + 1] = o1;
}
__global__ void f2h_all_kernel(const float* w0, __half* o0, int n0,   // in 16-elem units
                               const float* w1, __half* o1, int n1,
                               const float* w2, __half* o2, int n2,
                               const float* w3, __half* o3, int n3) {
    int i = blockIdx.x * blockDim.x + threadIdx.x;
    if (i < n0) { cvt16((const float4*)w0, (uint4*)o0, i); return; }
    i -= n0;
    if (i < n1) { cvt16((const float4*)w1, (uint4*)o1, i); return; }
    i -= n1;
    if (i < n2) { cvt16((const float4*)w2, (uint4*)o2, i); return; }
    i -= n2;
    if (i < n3) { cvt16((const float4*)w3, (uint4*)o3, i); }
}

// ---------------- LayerNorm: one WARP per row, half output -----------------
__global__ __launch_bounds__(256)
void ln_kernel(const float* __restrict__ x,
               const float* __restrict__ g,
               const float* __restrict__ b,
               __half* __restrict__ out) {
    const int lane = threadIdx.x & 31;
    const int row  = blockIdx.x * 8 + (threadIdx.x >> 5);
    const float* xr = x + (size_t)row * D_DIM;

    float4 v[8];
    float s = 0.f;
    #pragma unroll
    for (int i = 0; i < 8; i++) {
        v[i] = *(const float4*)(xr + i * 128 + lane * 4);
        s += v[i].x + v[i].y + v[i].z + v[i].w;
    }
    #pragma unroll
    for (int o = 16; o > 0; o >>= 1) s += __shfl_xor_sync(0xffffffffu, s, o);
    const float mean = s * (1.f / D_DIM);

    float var = 0.f;
    #pragma unroll
    for (int i = 0; i < 8; i++) {
        float dx = v[i].x - mean, dy = v[i].y - mean;
        float dz = v[i].z - mean, dw = v[i].w - mean;
        var += dx * dx + dy * dy + dz * dz + dw * dw;
    }
    #pragma unroll
    for (int o = 16; o > 0; o >>= 1) var += __shfl_xor_sync(0xffffffffu, var, o);
    const float rstd = rsqrtf(var * (1.f / D_DIM) + EPS);

    __half* orow = out + (size_t)row * D_DIM;
    #pragma unroll
    for (int i = 0; i < 8; i++) {
        const int col = i * 128 + lane * 4;
        float4 gv = *(const float4*)(g + col);
        float4 bv = *(const float4*)(b + col);
        uint2 o;
        o.x = h2pack((v[i].x - mean) * rstd * gv.x + bv.x,
                     (v[i].y - mean) * rstd * gv.y + bv.y);
        o.y = h2pack((v[i].z - mean) * rstd * gv.z + bv.z,
                     (v[i].w - mean) * rstd * gv.w + bv.w);
        *(uint2*)(orow + col) = o;
    }
}

// ------- FP16 GEMM: 128x128 tile, BK=64, 2-stage cp.async (race-free) ------
// Order per iter: wait -> barrier -> issue next loads -> compute.
// EPI: 0 = bias (CT out), 1 = bias + exact GELU (half C), 2 = bias+resid (float C)
#define G3_AS_HALFS (2 * 128 * 72)
#define G3_SMEM_BYTES ((2 * 128 * 72 + 2 * 64 * 136) * 2)   // 71680
template<int EPI, typename CT>
__global__ __launch_bounds__(256)
void gemm_f16_kernel(const __half* __restrict__ A,
                     const __half* __restrict__ B,
                     const float* __restrict__ bias,
                     const float* __restrict__ resid,
                     CT* __restrict__ C,
                     int M, int N, int K) {
    extern __shared__ __half gsm[];
    __half (*As)[128][72] = (__half(*)[128][72])gsm;
    __half (*Bs)[64][136] = (__half(*)[64][136])(gsm + G3_AS_HALFS);

    const int tid  = threadIdx.x;
    const int lane = tid & 31;
    const int wid  = tid >> 5;
    const int warp_m = wid & 1;
    const int warp_n = wid >> 1;
    const int g = lane >> 2;
    const int t = lane & 3;

    const int bx = blockIdx.x;
    const int by = blockIdx.y;

    const __half* Ag = A + (size_t)by * 128 * K;
    const __half* Bg = B + (size_t)bx * 128;

    float acc[4][4][4];
    #pragma unroll
    for (int mi = 0; mi < 4; mi++)
        #pragma unroll
        for (int ni = 0; ni < 4; ni++)
            #pragma unroll
            for (int e = 0; e < 4; e++) acc[mi][ni][e] = 0.f;

    const int NIT = K >> 6;    // BK = 64

    auto load_stage = [&](int st, int k0) {
        #pragma unroll
        for (int i = 0; i < 4; i++) {
            int id = tid + 256 * i;
            int r = id >> 3, c = (id & 7) * 8;
            cp16(&As[st][r][c], Ag + (size_t)r * K + k0 + c);
        }
        #pragma unroll
        for (int i = 0; i < 4; i++) {
            int id = tid + 256 * i;
            int r = id >> 4, c = (id & 15) * 8;
            cp16(&Bs[st][r][c], Bg + (size_t)(k0 + r) * N + c);
        }
        cp_commit();
    };

    load_stage(0, 0);

    const int a_row = lane & 15;
    const int a_chk = (lane >> 4) * 8;

    #pragma unroll 1
    for (int it = 0; it < NIT; it++) {
        const int buf = it & 1;
        asm volatile("cp.async.wait_group 0;\n");
        __syncthreads();
        if (it + 1 < NIT) load_stage(buf ^ 1, (it + 1) << 6);

        #pragma unroll
        for (int ks = 0; ks < 4; ks++) {
            uint32_t af[4][4], bf[4][2];
            #pragma unroll
            for (int mi = 0; mi < 4; mi++) {
                int row = warp_m * 64 + mi * 16 + a_row;
                ldsm_x4(af[mi], &As[buf][row][ks * 16 + a_chk]);
            }
            #pragma unroll
            for (int p = 0; p < 2; p++) {
                uint32_t r[4];
                int krow = ks * 16 + a_row;
                int ncol = warp_n * 32 + p * 16 + a_chk;
                ldsm_x4_t(r, &Bs[buf][krow][ncol]);
                bf[p * 2][0] = r[0]; bf[p * 2][1] = r[1];
                bf[p * 2 + 1][0] = r[2]; bf[p * 2 + 1][1] = r[3];
            }
            #pragma unroll
            for (int mi = 0; mi < 4; mi++)
                #pragma unroll
                for (int ni = 0; ni < 4; ni++)
                    mma_f16(acc[mi][ni], af[mi], bf[ni]);
        }
    }

    #pragma unroll
    for (int mi = 0; mi < 4; mi++) {
        const int row0 = by * 128 + warp_m * 64 + mi * 16 + g;
        #pragma unroll
        for (int ni = 0; ni < 4; ni++) {
            const int col = bx * 128 + warp_n * 32 + (ni >> 1) * 16 + (ni & 1) * 8 + 2 * t;
            #pragma unroll
            for (int half_ = 0; half_ < 2; half_++) {
                const int r = row0 + half_ * 8;
                float v0 = acc[mi][ni][half_ * 2]     + bias[col];
                float v1 = acc[mi][ni][half_ * 2 + 1] + bias[col + 1];
                if (EPI == 1) {
                    v0 = 0.5f * v0 * (1.f + erff(v0 * 0.70710678118654752f));
                    v1 = 0.5f * v1 * (1.f + erff(v1 * 0.70710678118654752f));
                } else if (EPI == 2) {
                    const float* rr = resid + (size_t)r * N + col;
                    v0 += rr[0]; v1 += rr[1];
                }
                if (sizeof(CT) == 2) {
                    *(uint32_t*)((__half*)C + (size_t)r * N + col) = h2pack(v0, v1);
                } else {
                    ((float*)C)[(size_t)r * N + col]     = v0;
                    ((float*)C)[(size_t)r * N + col + 1] = v1;
                }
            }
        }
    }
}

// ---------------- RoPE on q and k slices of half qkv ----------------
__global__ void rope_kernel(__half* __restrict__ qkv,
                            const float* __restrict__ cosp,
                            const float* __restrict__ sinp) {
    int idx = blockIdx.x * blockDim.x + threadIdx.x;  // S*H*16
    if (idx >= S_LEN * H_NUM * 16) return;
    const int d2 = (idx & 15) * 2;
    const int h = (idx >> 4) & (H_NUM - 1);
    const int s = idx >> 8;

    const float2 c1 = *(const float2*)(cosp + s * 64 + d2);
    const float2 c2 = *(const float2*)(cosp + s * 64 + d2 + 32);
    const float2 s1 = *(const float2*)(sinp + s * 64 + d2);
    const float2 s2 = *(const float2*)(sinp + s * 64 + d2 + 32);

    __half* base = qkv + (size_t)s * (3 * D_DIM) + h * HD_DIM + d2;
    #pragma unroll
    for (int qk = 0; qk < 2; qk++) {
        __half* p = base + qk * D_DIM;
        float2 a = __half22float2(*(__half2*)p);
        float2 bv = __half22float2(*(__half2*)(p + 32));
        *(uint32_t*)p        = h2pack(a.x * c1.x - bv.x * s1.x,
                                      a.y * c1.y - bv.y * s1.y);
        *(uint32_t*)(p + 32) = h2pack(bv.x * c2.x + a.x * s2.x,
                                      bv.y * c2.y + a.y * s2.y);
    }
}

// ---- fp16 flash attention, double-buffered cp.async K/V chunks ----
__global__ __launch_bounds__(256)
void attn_kernel(const __half* __restrict__ qkv,
                 const int* __restrict__ cu,
                 __half* __restrict__ ao) {
    const int h  = blockIdx.y;
    const int s0 = blockIdx.x * 128;
    const int tid  = threadIdx.x;
    const int lane = tid & 31;
    const int wid  = tid >> 5;
    const int g = lane >> 2;
    const int t = lane & 3;
    const int a_row = lane & 15;
    const int a_chk = (lane >> 4) * 8;

    __shared__ __half Kh[2][32][72];
    __shared__ __half Vh[2][32][72];

    int start = 0, len = S_LEN;
    #pragma unroll
    for (int i = 0; i < NSEG; i++) {
        int a = cu[i], b = cu[i + 1];
        if (s0 >= a && s0 < b) { start = a; len = b - a; }
    }

    const int pr = wid * 16;

    uint32_t qf[4][4];
    {
        const __half* q0 = qkv + (size_t)(s0 + pr + g) * (3 * D_DIM) + h * HD_DIM;
        const __half* q8 = q0 + 8 * (3 * D_DIM);
        #pragma unroll
        for (int dc = 0; dc < 4; dc++) {
            const int c = dc * 16 + 2 * t;
            qf[dc][0] = *(const uint32_t*)(q0 + c);
            qf[dc][1] = *(const uint32_t*)(q8 + c);
            qf[dc][2] = *(const uint32_t*)(q0 + c + 8);
            qf[dc][3] = *(const uint32_t*)(q8 + c + 8);
        }
    }

    float m0 = -3.4e38f, m1 = -3.4e38f, l0 = 0.f, l1 = 0.f;
    float out[8][4];
    #pragma unroll
    for (int n = 0; n < 8; n++)
        #pragma unroll
        for (int e = 0; e < 4; e++) out[n][e] = 0.f;

    const int kr = tid >> 3;
    const int kc8 = (tid & 7) * 8;
    auto load_chunk = [&](int buf, int kb) {
        const __half* base = qkv + (size_t)(kb + kr) * (3 * D_DIM) + h * HD_DIM + kc8;
        cp16(&Kh[buf][kr][kc8], base + D_DIM);
        cp16(&Vh[buf][kr][kc8], base + 2 * D_DIM);
        cp_commit();
    };

    load_chunk(0, start);

    const int nch = len >> 5;
    for (int c = 0; c < nch; c++) {
        const int buf = c & 1;
        asm volatile("cp.async.wait_group 0;\n");
        __syncthreads();
        if (c + 1 < nch) load_chunk(buf ^ 1, start + (c + 1) * 32);

        // S = Q @ K^T
        float sacc[4][4];
        #pragma unroll
        for (int j = 0; j < 4; j++)
            #pragma unroll
            for (int e = 0; e < 4; e++) sacc[j][e] = 0.f;
        #pragma unroll
        for (int dc = 0; dc < 4; dc++) {
            #pragma unroll
            for (int kh = 0; kh < 2; kh++) {
                uint32_t r[4];
                ldsm_x4(r, &Kh[buf][kh * 16 + a_row][dc * 16 + a_chk]);
                mma_f16_2(sacc[kh * 2],     qf[dc][0], qf[dc][1], qf[dc][2], qf[dc][3],
                          r[0], r[2]);
                mma_f16_2(sacc[kh * 2 + 1], qf[dc][0], qf[dc][1], qf[dc][2], qf[dc][3],
                          r[1], r[3]);
            }
        }
        #pragma unroll
        for (int j = 0; j < 4; j++)
            #pragma unroll
            for (int e = 0; e < 4; e++) sacc[j][e] *= 0.125f;

        // online softmax
        float ml0 = -3.4e38f, ml1 = -3.4e38f;
        #pragma unroll
        for (int j = 0; j < 4; j++) {
            ml0 = fmaxf(ml0, fmaxf(sacc[j][0], sacc[j][1]));
            ml1 = fmaxf(ml1, fmaxf(sacc[j][2], sacc[j][3]));
        }
        ml0 = fmaxf(ml0, __shfl_xor_sync(0xffffffffu, ml0, 1));
        ml0 = fmaxf(ml0, __shfl_xor_sync(0xffffffffu, ml0, 2));
        ml1 = fmaxf(ml1, __shfl_xor_sync(0xffffffffu, ml1, 1));
        ml1 = fmaxf(ml1, __shfl_xor_sync(0xffffffffu, ml1, 2));
        const float mn0 = fmaxf(m0, ml0);
        const float mn1 = fmaxf(m1, ml1);
        const float f0 = __expf(m0 - mn0);
        const float f1 = __expf(m1 - mn1);

        uint32_t pa[2][4];
        float ll0 = 0.f, ll1 = 0.f;
        #pragma unroll
        for (int j = 0; j < 4; j++) {
            float p0 = __expf(sacc[j][0] - mn0);
            float p1 = __expf(sacc[j][1] - mn0);
            float p2 = __expf(sacc[j][2] - mn1);
            float p3 = __expf(sacc[j][3] - mn1);
            ll0 += p0 + p1; ll1 += p2 + p3;
            pa[j >> 1][(j & 1) * 2]     = h2pack(p0, p1);
            pa[j >> 1][(j & 1) * 2 + 1] = h2pack(p2, p3);
        }
        ll0 += __shfl_xor_sync(0xffffffffu, ll0, 1);
        ll0 += __shfl_xor_sync(0xffffffffu, ll0, 2);
        ll1 += __shfl_xor_sync(0xffffffffu, ll1, 1);
        ll1 += __shfl_xor_sync(0xffffffffu, ll1, 2);
        l0 = l0 * f0 + ll0;
        l1 = l1 * f1 + ll1;
        m0 = mn0; m1 = mn1;
        #pragma unroll
        for (int n = 0; n < 8; n++) {
            out[n][0] *= f0; out[n][1] *= f0;
            out[n][2] *= f1; out[n][3] *= f1;
        }

        // out += P @ V
        #pragma unroll
        for (int kc = 0; kc < 2; kc++) {
            #pragma unroll
            for (int p = 0; p < 4; p++) {
                uint32_t r[4];
                ldsm_x4_t(r, &Vh[buf][kc * 16 + a_row][p * 16 + a_chk]);
                mma_f16(out[p * 2], pa[kc], r);
                mma_f16_2(out[p * 2 + 1], pa[kc][0], pa[kc][1], pa[kc][2], pa[kc][3],
                          r[2], r[3]);
            }
        }
    }

    const float i0 = 1.f / l0;
    const float i1 = 1.f / l1;
    __half* o0 = ao + (size_t)(s0 + pr + g) * D_DIM + h * HD_DIM;
    __half* o8 = o0 + 8 * D_DIM;
    #pragma unroll
    for (int n = 0; n < 8; n++) {
        *(uint32_t*)(o0 + 8 * n + 2 * t) = h2pack(out[n][0] * i0, out[n][1] * i0);
        *(uint32_t*)(o8 + 8 * n + 2 * t) = h2pack(out[n][2] * i1, out[n][3] * i1);
    }
}

// ---------------- driver ----------------
extern "C" void kernel_launch(void* const* d_in, const int* in_sizes, int n_in,
                              void* d_out, int out_size) {
    const float* hidden = (const float*)d_in[0];
    const int*   cu     = (const int*)d_in[1];
    const float* cosp   = (const float*)d_in[2];
    const float* sinp   = (const float*)d_in[3];
    const float* ln1_g  = (const float*)d_in[4];
    const float* ln1_b  = (const float*)d_in[5];
    const float* qkv_w  = (const float*)d_in[6];
    const float* qkv_b  = (const float*)d_in[7];
    const float* proj_w = (const float*)d_in[8];
    const float* proj_b = (const float*)d_in[9];
    const float* ln2_g  = (const float*)d_in[10];
    const float* ln2_b  = (const float*)d_in[11];
    const float* fc1_w  = (const float*)d_in[12];
    const float* fc1_b  = (const float*)d_in[13];
    const float* fc2_w  = (const float*)d_in[14];
    const float* fc2_b  = (const float*)d_in[15];

    float* x = (float*)d_out;

    __half *h, *qkv, *ao, *ff, *wq, *wp, *w1, *w2;
    cudaGetSymbolAddress((void**)&h,   g_h);
    cudaGetSymbolAddress((void**)&qkv, g_qkv);
    cudaGetSymbolAddress((void**)&ao,  g_ao);
    cudaGetSymbolAddress((void**)&ff,  g_ff);
    cudaGetSymbolAddress((void**)&wq,  g_wq);
    cudaGetSymbolAddress((void**)&wp,  g_wp);
    cudaGetSymbolAddress((void**)&w1,  g_w1);
    cudaGetSymbolAddress((void**)&w2,  g_w2);

    cudaFuncSetAttribute(gemm_f16_kernel<0, __half>,
                         cudaFuncAttributeMaxDynamicSharedMemorySize, G3_SMEM_BYTES);
    cudaFuncSetAttribute(gemm_f16_kernel<1, __half>,
                         cudaFuncAttributeMaxDynamicSharedMemorySize, G3_SMEM_BYTES);
    cudaFuncSetAttribute(gemm_f16_kernel<2, float>,
                         cudaFuncAttributeMaxDynamicSharedMemorySize, G3_SMEM_BYTES);

    // fused weight conversion (fp32 -> fp16), 16 elems/thread
    {
        const int n0 = DEPTH * D_DIM * 3 * D_DIM / 16;
        const int n1 = DEPTH * D_DIM * D_DIM / 16;
        const int n2 = DEPTH * D_DIM * FF_DIM / 16;
        const int n3 = DEPTH * FF_DIM * D_DIM / 16;
        const int total = n0 + n1 + n2 + n3;
        f2h_all_kernel<<<(total + 255) / 256, 256>>>(
            qkv_w, wq, n0, proj_w, wp, n1, fc1_w, w1, n2, fc2_w, w2, n3);
    }

    cudaMemcpyAsync(x, hidden, (size_t)S_LEN * D_DIM * sizeof(float),
                    cudaMemcpyDeviceToDevice);

    for (int i = 0; i < DEPTH; i++) {
        const __half* wqi = wq + (size_t)i * D_DIM * 3 * D_DIM;
        const float*  qb  = qkv_b  + (size_t)i * 3 * D_DIM;
        const __half* wpi = wp + (size_t)i * D_DIM * D_DIM;
        const float*  pb  = proj_b + (size_t)i * D_DIM;
        const __half* w1i = w1 + (size_t)i * D_DIM * FF_DIM;
        const float*  f1b = fc1_b  + (size_t)i * FF_DIM;
        const __half* w2i = w2 + (size_t)i * FF_DIM * D_DIM;
        const float*  f2b = fc2_b  + (size_t)i * D_DIM;

        ln_kernel<<<S_LEN / 8, 256>>>(x, ln1_g + (size_t)i * D_DIM,
                                      ln1_b + (size_t)i * D_DIM, h);

        {   // qkv = h @ qkv_w + qkv_b  (half out)
            dim3 grid(3 * D_DIM / 128, S_LEN / 128);
            gemm_f16_kernel<0, __half><<<grid, 256, G3_SMEM_BYTES>>>(
                h, wqi, qb, nullptr, qkv, S_LEN, 3 * D_DIM, D_DIM);
        }

        {   // RoPE (half)
            int total = S_LEN * H_NUM * 16;
            rope_kernel<<<(total + 255) / 256, 256>>>(qkv, cosp, sinp);
        }

        {   // attention -> half ao
            dim3 grid(S_LEN / 128, H_NUM);
            attn_kernel<<<grid, 256>>>(qkv, cu, ao);
        }

        {   // x += ao @ proj_w + proj_b  (fp32 out)
            dim3 grid(D_DIM / 128, S_LEN / 128);
            gemm_f16_kernel<2, float><<<grid, 256, G3_SMEM_BYTES>>>(
                ao, wpi, pb, x, x, S_LEN, D_DIM, D_DIM);
        }

        ln_kernel<<<S_LEN / 8, 256>>>(x, ln2_g + (size_t)i * D_DIM,
                                      ln2_b + (size_t)i * D_DIM, h);

        {   // ff = gelu(h @ fc1_w + fc1_b)  (half out)
            dim3 grid(FF_DIM / 128, S_LEN / 128);
            gemm_f16_kernel<1, __half><<<grid, 256, G3_SMEM_BYTES>>>(
                h, w1i, f1b, nullptr, ff, S_LEN, FF_DIM, D_DIM);
        }

        {   // x += ff @ fc2_w + fc2_b  (fp32 out)
            dim3 grid(D_DIM / 128, S_LEN / 128);
            gemm_f16_kernel<2, float><<<grid, 256, G3_SMEM_BYTES>>>(
                ff, w2i, f2b, x, x, S_LEN, D_DIM, FF_DIM);
        }
    }
}